// round 9
// baseline (speedup 1.0000x reference)
#include <cuda_runtime.h>

#define NN 1048576
#define EE 8388608
#define GG 32768
#define PS 12   // padded row stride (9 ch + 3 pad) -> 48B, 16B-aligned
#define NZI 4                           // nodes/thread in stats kernels (fully unrolled)
#define NB_STAT (NN / (256 * NZI))      // 1024
#define NB_N (NN / 256)                 // 4096
#define NB_E (EE / 256)                 // 32768
#define NB_G (GG / 256)                 // 128

// ---------------- device state (no allocation allowed) ----------------
__device__ __align__(16) float  g_hin[(size_t)NN * PS];
__device__ __align__(16) float  g_buf[(size_t)NN * PS];
__device__ __align__(16) float  g_vn [(size_t)GG * PS];
__device__ __align__(16) float  g_gs [(size_t)GG * PS];
__device__ unsigned char g_eb[(size_t)EE];   // packed edge attr codes (<216)
// per-layer raw BN stats: sum at [c], sumsq at [18+c], 36-stride per layer
__device__ double g_stZ1[3 * 36];   // z@W1+b1, 18 ch
__device__ double g_stZ2[3 * 36];   // z2, 9 ch
__device__ double g_stV1[2 * 36];   // vn MLP hidden, 18 ch
__device__ double g_stV2[2 * 36];   // vn MLP out, 9 ch
__device__ double g_outacc[9];

// ---------------- helpers ----------------
__device__ __forceinline__ void red_add4(float* p, float a, float b, float c, float d) {
    asm volatile("red.global.add.v4.f32 [%0], {%1,%2,%3,%4};"
                 :: "l"(__cvta_generic_to_global(p)), "f"(a), "f"(b), "f"(c), "f"(d) : "memory");
}
__device__ __forceinline__ void red_add1(float* p, float a) {
    asm volatile("red.global.add.f32 [%0], %1;"
                 :: "l"(__cvta_generic_to_global(p)), "f"(a) : "memory");
}
__device__ __forceinline__ float warp_sum(float v) {
    #pragma unroll
    for (int off = 16; off > 0; off >>= 1) v += __shfl_down_sync(0xffffffffu, v, off);
    return v;
}

// warp-level segmented sum over sorted keys, then 3 vector atomics per segment head
__device__ __forceinline__ void seg_atomic9(int key, float v[9], float* dstBase) {
    int lane = threadIdx.x & 31;
    #pragma unroll
    for (int off = 1; off < 32; off <<= 1) {
        int nk = __shfl_down_sync(0xffffffffu, key, off);
        float t[9];
        #pragma unroll
        for (int k = 0; k < 9; k++) t[k] = __shfl_down_sync(0xffffffffu, v[k], off);
        if (lane + off < 32 && nk == key) {
            #pragma unroll
            for (int k = 0; k < 9; k++) v[k] += t[k];
        }
    }
    int pk = __shfl_up_sync(0xffffffffu, key, 1);
    if (lane == 0 || pk != key) {
        float* p = dstBase + (size_t)key * PS;
        red_add4(p,     v[0], v[1], v[2], v[3]);
        red_add4(p + 4, v[4], v[5], v[6], v[7]);
        red_add1(p + 8, v[8]);
    }
}

// inline BN param computation: threads c<C write sP[c]=scale, sP[C+c]=shift.
// Caller must __syncthreads() afterwards.
__device__ __forceinline__ void compute_bn(const double* st, int C, double inv,
                                           const float* gamma, const float* beta,
                                           float* sP) {
    int c = threadIdx.x;
    if (c < C) {
        double mean = st[c] * inv;
        double var  = st[18 + c] * inv - mean * mean;
        float sc = __ldg(gamma + c) * rsqrtf((float)var + 1e-5f);
        sP[c] = sc;
        sP[C + c] = __ldg(beta + c) - (float)mean * sc;
    }
}

// flush register stats (C channels of s,q) to global double slot via smem
__device__ __forceinline__ void stats_flush(const float* s, const float* q, int C,
                                            double* st, float* racc) {
    int lane = threadIdx.x & 31;
    for (int c = 0; c < C; c++) {
        float ss = warp_sum(s[c]);
        float qq = warp_sum(q[c]);
        if (lane == 0) { atomicAdd(&racc[c], ss); atomicAdd(&racc[18 + c], qq); }
    }
    __syncthreads();
    int t = threadIdx.x;
    if (t < C) atomicAdd(&st[t], (double)racc[t]);
    if (t >= 18 && t < 18 + C) atomicAdd(&st[t], (double)racc[t]);
}

// ---------------- kernels ----------------
__global__ void __launch_bounds__(256) k_init() {
    int i = blockIdx.x * 256 + threadIdx.x;
    if (i < GG * PS) { g_vn[i] = 0.f; g_gs[i] = 0.f; }
    if (i < 108) { g_stZ1[i] = 0.0; g_stZ2[i] = 0.0; }
    if (i < 72)  { g_stV1[i] = 0.0; g_stV2[i] = 0.0; }
    if (i < 9)   g_outacc[i] = 0.0;
}

// pack edge attrs: code = a0 + 6*a1 + 36*a2  (< 216), 1 byte per edge
__global__ void __launch_bounds__(256) k_pack(const int* __restrict__ ea) {
    int e = blockIdx.x * 256 + threadIdx.x;   // grid exactly covers EE
    int a0 = __ldg(ea + (size_t)3 * e);
    int a1 = __ldg(ea + (size_t)3 * e + 1);
    int a2 = __ldg(ea + (size_t)3 * e + 2);
    g_eb[e] = (unsigned char)(a0 + 6 * a1 + 36 * a2);
}

// AtomEncoder: h_in = sum_f atom_emb[f, x[n,f]]; zero msg buffer; graph sums of h_in
__global__ void __launch_bounds__(256) k_atom(const float* __restrict__ atom_emb,
                                              const int* __restrict__ x,
                                              const int* __restrict__ batch) {
    int n = blockIdx.x * 256 + threadIdx.x;   // grid exactly covers NN
    float h[9];
    #pragma unroll
    for (int k = 0; k < 9; k++) h[k] = 0.f;
    #pragma unroll
    for (int f = 0; f < 9; f++) {
        int v = __ldg(x + (size_t)n * 9 + f);
        const float* row = atom_emb + ((size_t)f * 119 + v) * 9;
        #pragma unroll
        for (int k = 0; k < 9; k++) h[k] += __ldg(row + k);
    }
    float4* hp = (float4*)(g_hin + (size_t)n * PS);
    hp[0] = make_float4(h[0], h[1], h[2], h[3]);
    hp[1] = make_float4(h[4], h[5], h[6], h[7]);
    hp[2] = make_float4(h[8], 0.f, 0.f, 0.f);
    float4 zz = make_float4(0.f, 0.f, 0.f, 0.f);
    float4* bp = (float4*)(g_buf + (size_t)n * PS);
    bp[0] = zz; bp[1] = zz; bp[2] = zz;
    int g = __ldg(batch + n);
    seg_atomic9(g, h, g_gs);
}

// GIN message: relu(h_in[src] + bondtable[code]) scatter-added at dst.
// Combined bond table (b0+b1+b2 presummed, 216 codes) built in smem, rows stride 12.
__global__ void __launch_bounds__(256) k_edge(const float* __restrict__ bond,
                                              const int* __restrict__ src,
                                              const int* __restrict__ dst) {
    __shared__ __align__(16) float T[216 * 12];
    for (int i = threadIdx.x; i < 216 * 9; i += 256) {
        int code = i / 9, k = i % 9;
        int a0 = code % 6, a1 = (code / 6) % 6, a2 = code / 36;
        T[code * 12 + k] = __ldg(bond + a0 * 9 + k) + __ldg(bond + 54 + a1 * 9 + k)
                         + __ldg(bond + 108 + a2 * 9 + k);
    }
    __syncthreads();
    int e = blockIdx.x * 256 + threadIdx.x;   // grid exactly covers EE
    int s = __ldg(src + e);
    int d = __ldg(dst + e);
    int code = (int)g_eb[e];
    const float4* hp = (const float4*)(g_hin + (size_t)s * PS);
    float4 h0 = hp[0], h1 = hp[1], h2 = hp[2];
    const float4* tp = (const float4*)(T + code * 12);
    float4 t0 = tp[0], t1 = tp[1], t2 = tp[2];
    float m0 = fmaxf(h0.x + t0.x, 0.f), m1 = fmaxf(h0.y + t0.y, 0.f);
    float m2 = fmaxf(h0.z + t0.z, 0.f), m3 = fmaxf(h0.w + t0.w, 0.f);
    float m4 = fmaxf(h1.x + t1.x, 0.f), m5 = fmaxf(h1.y + t1.y, 0.f);
    float m6 = fmaxf(h1.z + t1.z, 0.f), m7 = fmaxf(h1.w + t1.w, 0.f);
    float m8 = fmaxf(h2.x + t2.x, 0.f);
    float* p = g_buf + (size_t)d * PS;
    red_add4(p,     m0, m1, m2, m3);
    red_add4(p + 4, m4, m5, m6, m7);
    red_add1(p + 8, m8);
}

// z = (1+eps)*h_in + aggr ; write z ; register-accumulated stats of z@W1+b1 (18 ch)
// NZI nodes/thread FULLY UNROLLED (ILP over occupancy: R6 evidence 47.8us @ 255 regs)
__global__ void __launch_bounds__(256) k_nodeZ(const float* __restrict__ W1,
                                               const float* __restrict__ b1,
                                               const float* __restrict__ eps_ptr, int l) {
    __shared__ float sW[162], sb[18], racc[36];
    int t = threadIdx.x;
    if (t < 162) sW[t] = W1[t];
    if (t < 18)  sb[t] = b1[t];
    if (t < 36)  racc[t] = 0.f;
    __syncthreads();
    float eps1 = 1.f + __ldg(eps_ptr);
    float s[18], q[18];
    #pragma unroll
    for (int c = 0; c < 18; c++) { s[c] = 0.f; q[c] = 0.f; }
    int base = blockIdx.x * (256 * NZI) + t;
    #pragma unroll
    for (int i = 0; i < NZI; i++) {
        int n = base + i * 256;
        float4* bp = (float4*)(g_buf + (size_t)n * PS);
        const float4* hp = (const float4*)(g_hin + (size_t)n * PS);
        float4 a = bp[0], b4 = bp[1], c4 = bp[2];
        float4 ha = hp[0], hb = hp[1], hc = hp[2];
        float z[9];
        z[0] = fmaf(eps1, ha.x, a.x);  z[1] = fmaf(eps1, ha.y, a.y);
        z[2] = fmaf(eps1, ha.z, a.z);  z[3] = fmaf(eps1, ha.w, a.w);
        z[4] = fmaf(eps1, hb.x, b4.x); z[5] = fmaf(eps1, hb.y, b4.y);
        z[6] = fmaf(eps1, hb.z, b4.z); z[7] = fmaf(eps1, hb.w, b4.w);
        z[8] = fmaf(eps1, hc.x, c4.x);
        bp[0] = make_float4(z[0], z[1], z[2], z[3]);
        bp[1] = make_float4(z[4], z[5], z[6], z[7]);
        bp[2] = make_float4(z[8], 0.f, 0.f, 0.f);
        #pragma unroll
        for (int c = 0; c < 18; c++) {
            float z1 = sb[c];
            #pragma unroll
            for (int j = 0; j < 9; j++) z1 = fmaf(z[j], sW[j * 18 + c], z1);
            s[c] += z1;
            q[c] = fmaf(z1, z1, q[c]);
        }
    }
    stats_flush(s, q, 18, g_stZ1 + l * 36, racc);
}

// y = relu(BN1(z@W1+b1)) (params inline); z2 = y@W2+b2; write z2; stats of z2 (9 ch)
__global__ void __launch_bounds__(256) k_nodeY(const float* __restrict__ W1,
                                               const float* __restrict__ b1,
                                               const float* __restrict__ W2,
                                               const float* __restrict__ b2,
                                               const float* __restrict__ bn1_g,
                                               const float* __restrict__ bn1_b, int l) {
    __shared__ float sW1[162], sW2[162], sb1[18], sb2[9], sP[36], racc[36];
    int t = threadIdx.x;
    if (t < 162) { sW1[t] = W1[t]; sW2[t] = W2[t]; }
    if (t < 18) sb1[t] = b1[t];
    if (t < 9)  sb2[t] = b2[t];
    if (t < 36) racc[t] = 0.f;
    compute_bn(g_stZ1 + l * 36, 18, 1.0 / (double)NN, bn1_g, bn1_b, sP);
    __syncthreads();
    float s[9], q[9];
    #pragma unroll
    for (int c = 0; c < 9; c++) { s[c] = 0.f; q[c] = 0.f; }
    int base = blockIdx.x * (256 * NZI) + t;
    #pragma unroll
    for (int i = 0; i < NZI; i++) {
        int n = base + i * 256;
        float4* bp = (float4*)(g_buf + (size_t)n * PS);
        float4 a = bp[0], b4 = bp[1], c4 = bp[2];
        float z[9] = {a.x, a.y, a.z, a.w, b4.x, b4.y, b4.z, b4.w, c4.x};
        float z2[9];
        #pragma unroll
        for (int c = 0; c < 9; c++) z2[c] = sb2[c];
        #pragma unroll
        for (int c = 0; c < 18; c++) {
            float z1 = sb1[c];
            #pragma unroll
            for (int j = 0; j < 9; j++) z1 = fmaf(z[j], sW1[j * 18 + c], z1);
            float y = fmaxf(fmaf(z1, sP[c], sP[18 + c]), 0.f);
            #pragma unroll
            for (int j = 0; j < 9; j++) z2[j] = fmaf(y, sW2[c * 9 + j], z2[j]);
        }
        bp[0] = make_float4(z2[0], z2[1], z2[2], z2[3]);
        bp[1] = make_float4(z2[4], z2[5], z2[6], z2[7]);
        bp[2] = make_float4(z2[8], 0.f, 0.f, 0.f);
        #pragma unroll
        for (int c = 0; c < 9; c++) {
            s[c] += z2[c];
            q[c] = fmaf(z2[c], z2[c], q[c]);
        }
    }
    stats_flush(s, q, 9, g_stZ2 + l * 36, racc);
}

// VN step A: vn_tmp = graphsum + vn (stored back into g_gs); stats of vn_tmp@vnW1+vnb1
__global__ void __launch_bounds__(256) k_vnA(const float* __restrict__ W1,
                                             const float* __restrict__ b1, int l) {
    __shared__ float sW[162], sb[18], racc[36];
    int t = threadIdx.x;
    if (t < 162) sW[t] = W1[t];
    if (t < 18)  sb[t] = b1[t];
    if (t < 36)  racc[t] = 0.f;
    __syncthreads();
    int g = blockIdx.x * 256 + t;
    float4* gp = (float4*)(g_gs + (size_t)g * PS);
    const float4* vp = (const float4*)(g_vn + (size_t)g * PS);
    float4 a = gp[0], b4 = gp[1], c4 = gp[2];
    float4 va = vp[0], vb = vp[1], vc = vp[2];
    float vt[9] = {a.x + va.x, a.y + va.y, a.z + va.z, a.w + va.w,
                   b4.x + vb.x, b4.y + vb.y, b4.z + vb.z, b4.w + vb.w, c4.x + vc.x};
    gp[0] = make_float4(vt[0], vt[1], vt[2], vt[3]);
    gp[1] = make_float4(vt[4], vt[5], vt[6], vt[7]);
    gp[2] = make_float4(vt[8], 0.f, 0.f, 0.f);
    float s[18], q[18];
    #pragma unroll
    for (int c = 0; c < 18; c++) {
        float u = sb[c];
        #pragma unroll
        for (int j = 0; j < 9; j++) u = fmaf(vt[j], sW[j * 18 + c], u);
        s[c] = u; q[c] = u * u;
    }
    stats_flush(s, q, 18, g_stV1 + l * 36, racc);
}

// VN step B: t = relu(BN1(u1)) (inline params); u2 = t@vnW2+vnb2 -> g_gs; stats of u2
__global__ void __launch_bounds__(256) k_vnB(const float* __restrict__ W1,
                                             const float* __restrict__ b1,
                                             const float* __restrict__ W2,
                                             const float* __restrict__ b2,
                                             const float* __restrict__ bn_g,
                                             const float* __restrict__ bn_b, int l) {
    __shared__ float sW1[162], sW2[162], sb1[18], sb2[9], sP[36], racc[36];
    int t = threadIdx.x;
    if (t < 162) { sW1[t] = W1[t]; sW2[t] = W2[t]; }
    if (t < 18) sb1[t] = b1[t];
    if (t < 9)  sb2[t] = b2[t];
    if (t < 36) racc[t] = 0.f;
    compute_bn(g_stV1 + l * 36, 18, 1.0 / (double)GG, bn_g, bn_b, sP);
    __syncthreads();
    int g = blockIdx.x * 256 + t;
    float4* gp = (float4*)(g_gs + (size_t)g * PS);
    float4 a = gp[0], b4 = gp[1], c4 = gp[2];
    float vt[9] = {a.x, a.y, a.z, a.w, b4.x, b4.y, b4.z, b4.w, c4.x};
    float u2[9];
    #pragma unroll
    for (int c = 0; c < 9; c++) u2[c] = sb2[c];
    #pragma unroll
    for (int c = 0; c < 18; c++) {
        float u = sb1[c];
        #pragma unroll
        for (int j = 0; j < 9; j++) u = fmaf(vt[j], sW1[j * 18 + c], u);
        float y = fmaxf(fmaf(u, sP[c], sP[18 + c]), 0.f);
        #pragma unroll
        for (int j = 0; j < 9; j++) u2[j] = fmaf(y, sW2[c * 9 + j], u2[j]);
    }
    gp[0] = make_float4(u2[0], u2[1], u2[2], u2[3]);
    gp[1] = make_float4(u2[4], u2[5], u2[6], u2[7]);
    gp[2] = make_float4(u2[8], 0.f, 0.f, 0.f);
    float s[9], q[9];
    #pragma unroll
    for (int c = 0; c < 9; c++) { s[c] = u2[c]; q[c] = u2[c] * u2[c]; }
    stats_flush(s, q, 9, g_stV2 + l * 36, racc);
}

// VN step C: vn += relu(BN2(u2)) (inline params); zero graph-sum buffer for next layer
__global__ void __launch_bounds__(256) k_vnC(const float* __restrict__ bn_g,
                                             const float* __restrict__ bn_b, int l) {
    __shared__ float sP[18];
    compute_bn(g_stV2 + l * 36, 9, 1.0 / (double)GG, bn_g, bn_b, sP);
    __syncthreads();
    int g = blockIdx.x * 256 + threadIdx.x;
    float4* gp = (float4*)(g_gs + (size_t)g * PS);
    float4* vp = (float4*)(g_vn + (size_t)g * PS);
    float4 a = gp[0], b4 = gp[1], c4 = gp[2];
    float u2[9] = {a.x, a.y, a.z, a.w, b4.x, b4.y, b4.z, b4.w, c4.x};
    float4 va = vp[0], vb = vp[1], vc = vp[2];
    float vo[9] = {va.x, va.y, va.z, va.w, vb.x, vb.y, vb.z, vb.w, vc.x};
    #pragma unroll
    for (int k = 0; k < 9; k++)
        vo[k] += fmaxf(fmaf(u2[k], sP[k], sP[9 + k]), 0.f);
    vp[0] = make_float4(vo[0], vo[1], vo[2], vo[3]);
    vp[1] = make_float4(vo[4], vo[5], vo[6], vo[7]);
    vp[2] = make_float4(vo[8], 0.f, 0.f, 0.f);
    float4 zz = make_float4(0.f, 0.f, 0.f, 0.f);
    gp[0] = zz; gp[1] = zz; gp[2] = zz;
}

// layer finish (l<2): h_new = relu(BNout(z2)) + h_in (inline params); h_in' = h_new + vn'[batch]
__global__ void __launch_bounds__(256) k_final_mid(const int* __restrict__ batch,
                                                   const float* __restrict__ bn_g,
                                                   const float* __restrict__ bn_b,
                                                   int l, int accumGS) {
    __shared__ float sP[18];
    compute_bn(g_stZ2 + l * 36, 9, 1.0 / (double)NN, bn_g, bn_b, sP);
    __syncthreads();
    int n = blockIdx.x * 256 + threadIdx.x;   // grid exactly covers NN
    float4* bp = (float4*)(g_buf + (size_t)n * PS);
    float4* hp = (float4*)(g_hin + (size_t)n * PS);
    float4 a = bp[0], b4 = bp[1], c4 = bp[2];
    float z2[9] = {a.x, a.y, a.z, a.w, b4.x, b4.y, b4.z, b4.w, c4.x};
    float4 ha = hp[0], hb = hp[1], hc = hp[2];
    float hi[9] = {ha.x, ha.y, ha.z, ha.w, hb.x, hb.y, hb.z, hb.w, hc.x};
    int g = __ldg(batch + n);
    const float4* vp = (const float4*)(g_vn + (size_t)g * PS);
    float4 va = vp[0], vb = vp[1], vc = vp[2];
    float vn9[9] = {va.x, va.y, va.z, va.w, vb.x, vb.y, vb.z, vb.w, vc.x};
    float hx[9];
    #pragma unroll
    for (int k = 0; k < 9; k++) {
        float zn = fmaxf(fmaf(z2[k], sP[k], sP[9 + k]), 0.f);
        hx[k] = zn + hi[k] + vn9[k];
    }
    hp[0] = make_float4(hx[0], hx[1], hx[2], hx[3]);
    hp[1] = make_float4(hx[4], hx[5], hx[6], hx[7]);
    hp[2] = make_float4(hx[8], 0.f, 0.f, 0.f);
    float4 zz = make_float4(0.f, 0.f, 0.f, 0.f);
    bp[0] = zz; bp[1] = zz; bp[2] = zz;
    if (accumGS) seg_atomic9(g, hx, g_gs);
}

// last layer finish: h = BNout(z2) + h_in (no relu, inline params); global sum
__global__ void __launch_bounds__(256) k_final_last(const float* __restrict__ bn_g,
                                                    const float* __restrict__ bn_b, int l) {
    __shared__ float sP[18], racc[9];
    compute_bn(g_stZ2 + l * 36, 9, 1.0 / (double)NN, bn_g, bn_b, sP);
    if (threadIdx.x < 9) racc[threadIdx.x] = 0.f;
    __syncthreads();
    float hs[9];
    #pragma unroll
    for (int k = 0; k < 9; k++) hs[k] = 0.f;
    int base = blockIdx.x * (256 * NZI) + threadIdx.x;
    #pragma unroll
    for (int i = 0; i < NZI; i++) {
        int n = base + i * 256;
        const float4* bp = (const float4*)(g_buf + (size_t)n * PS);
        const float4* hp = (const float4*)(g_hin + (size_t)n * PS);
        float4 a = bp[0], b4 = bp[1], c4 = bp[2];
        float z2[9] = {a.x, a.y, a.z, a.w, b4.x, b4.y, b4.z, b4.w, c4.x};
        float4 ha = hp[0], hb = hp[1], hc = hp[2];
        float hi[9] = {ha.x, ha.y, ha.z, ha.w, hb.x, hb.y, hb.z, hb.w, hc.x};
        #pragma unroll
        for (int k = 0; k < 9; k++)
            hs[k] += fmaf(z2[k], sP[k], sP[9 + k]) + hi[k];
    }
    int lane = threadIdx.x & 31;
    #pragma unroll
    for (int k = 0; k < 9; k++) {
        float v = warp_sum(hs[k]);
        if (lane == 0) atomicAdd(&racc[k], v);
    }
    __syncthreads();
    if (threadIdx.x < 9) atomicAdd(&g_outacc[threadIdx.x], (double)racc[threadIdx.x]);
}

__global__ void k_out(float* __restrict__ out) {
    if (threadIdx.x < 9) out[threadIdx.x] = (float)g_outacc[threadIdx.x];
}

// ---------------- host ----------------
extern "C" void kernel_launch(void* const* d_in, const int* in_sizes, int n_in,
                              void* d_out, int out_size) {
    const float* atom_emb = (const float*)d_in[0];
    const float* bond_emb = (const float*)d_in[1];
    const float* eps_gin  = (const float*)d_in[2];
    const float* W1       = (const float*)d_in[3];
    const float* b1       = (const float*)d_in[4];
    const float* bn1_g    = (const float*)d_in[5];
    const float* bn1_b    = (const float*)d_in[6];
    const float* W2       = (const float*)d_in[7];
    const float* b2       = (const float*)d_in[8];
    const float* bno_g    = (const float*)d_in[9];
    const float* bno_b    = (const float*)d_in[10];
    const float* vnW1     = (const float*)d_in[11];
    const float* vnb1     = (const float*)d_in[12];
    const float* vnbn1_g  = (const float*)d_in[13];
    const float* vnbn1_b  = (const float*)d_in[14];
    const float* vnW2     = (const float*)d_in[15];
    const float* vnb2     = (const float*)d_in[16];
    const float* vnbn2_g  = (const float*)d_in[17];
    const float* vnbn2_b  = (const float*)d_in[18];
    const int*   x        = (const int*)d_in[19];
    const int*   eidx     = (const int*)d_in[20];
    const int*   eattr    = (const int*)d_in[21];
    const int*   batch    = (const int*)d_in[22];
    (void)in_sizes; (void)n_in; (void)out_size;

    k_init<<<(GG * PS + 255) / 256, 256>>>();
    k_pack<<<NB_E, 256>>>(eattr);
    k_atom<<<NB_N, 256>>>(atom_emb, x, batch);

    for (int l = 0; l < 3; l++) {
        k_edge<<<NB_E, 256>>>(bond_emb + l * 162, eidx, eidx + EE);
        k_nodeZ<<<NB_STAT, 256>>>(W1 + l * 162, b1 + l * 18, eps_gin + l, l);
        k_nodeY<<<NB_STAT, 256>>>(W1 + l * 162, b1 + l * 18, W2 + l * 162, b2 + l * 9,
                                  bn1_g + l * 18, bn1_b + l * 18, l);
        if (l < 2) {
            k_vnA<<<NB_G, 256>>>(vnW1 + l * 162, vnb1 + l * 18, l);
            k_vnB<<<NB_G, 256>>>(vnW1 + l * 162, vnb1 + l * 18, vnW2 + l * 162,
                                 vnb2 + l * 9, vnbn1_g + l * 18, vnbn1_b + l * 18, l);
            k_vnC<<<NB_G, 256>>>(vnbn2_g + l * 9, vnbn2_b + l * 9, l);
            k_final_mid<<<NB_N, 256>>>(batch, bno_g + l * 9, bno_b + l * 9, l,
                                       (l == 0) ? 1 : 0);
        } else {
            k_final_last<<<NB_STAT, 256>>>(bno_g + l * 9, bno_b + l * 9, l);
        }
    }
    k_out<<<1, 32>>>((float*)d_out);
}

// round 10
// speedup vs baseline: 2.1854x; 2.1854x over previous
#include <cuda_runtime.h>

#define NN 1048576
#define EE 8388608
#define GG 32768
#define PS 12   // padded row stride (9 ch + 3 pad) -> 48B, 16B-aligned
#define NZI 8                           // nodes/thread in k_nodeZ (R6-proven full unroll)
#define NB_Z (NN / (256 * NZI))         // 512
#define NB_N (NN / 256)                 // 4096
#define NB_E (EE / 256)                 // 32768
#define NB_G (GG / 256)                 // 128

// ---------------- device state (no allocation allowed) ----------------
__device__ __align__(16) float  g_hin[(size_t)NN * PS];
__device__ __align__(16) float  g_buf[(size_t)NN * PS];
__device__ __align__(16) float  g_vn [(size_t)GG * PS];
__device__ __align__(16) float  g_gs [(size_t)GG * PS];
__device__ unsigned char g_eb[(size_t)EE];          // packed edge attr codes (<216)
__device__ __align__(16) float g_bt[216 * 12];      // combined bond table for current layer
// per-layer raw BN stats: sum at [c], sumsq at [18+c], 36-stride per layer
__device__ double g_stZ1[3 * 36];   // z@W1+b1, 18 ch
__device__ double g_stZ2[3 * 36];   // z2, 9 ch
__device__ double g_stV1[2 * 36];   // vn MLP hidden, 18 ch
__device__ double g_stV2[2 * 36];   // vn MLP out, 9 ch
__device__ double g_outacc[9];

// ---------------- helpers ----------------
__device__ __forceinline__ void red_add4(float* p, float a, float b, float c, float d) {
    asm volatile("red.global.add.v4.f32 [%0], {%1,%2,%3,%4};"
                 :: "l"(__cvta_generic_to_global(p)), "f"(a), "f"(b), "f"(c), "f"(d) : "memory");
}
__device__ __forceinline__ void red_add1(float* p, float a) {
    asm volatile("red.global.add.f32 [%0], %1;"
                 :: "l"(__cvta_generic_to_global(p)), "f"(a) : "memory");
}
__device__ __forceinline__ float warp_sum(float v) {
    #pragma unroll
    for (int off = 16; off > 0; off >>= 1) v += __shfl_down_sync(0xffffffffu, v, off);
    return v;
}

// warp-level segmented sum over sorted keys, then 3 vector atomics per segment head
__device__ __forceinline__ void seg_atomic9(int key, float v[9], float* dstBase) {
    int lane = threadIdx.x & 31;
    #pragma unroll
    for (int off = 1; off < 32; off <<= 1) {
        int nk = __shfl_down_sync(0xffffffffu, key, off);
        float t[9];
        #pragma unroll
        for (int k = 0; k < 9; k++) t[k] = __shfl_down_sync(0xffffffffu, v[k], off);
        if (lane + off < 32 && nk == key) {
            #pragma unroll
            for (int k = 0; k < 9; k++) v[k] += t[k];
        }
    }
    int pk = __shfl_up_sync(0xffffffffu, key, 1);
    if (lane == 0 || pk != key) {
        float* p = dstBase + (size_t)key * PS;
        red_add4(p,     v[0], v[1], v[2], v[3]);
        red_add4(p + 4, v[4], v[5], v[6], v[7]);
        red_add1(p + 8, v[8]);
    }
}

// inline BN param computation: threads c<C write sP[c]=scale, sP[C+c]=shift.
// Caller must __syncthreads() afterwards.
__device__ __forceinline__ void compute_bn(const double* st, int C, double inv,
                                           const float* gamma, const float* beta,
                                           float* sP) {
    int c = threadIdx.x;
    if (c < C) {
        double mean = st[c] * inv;
        double var  = st[18 + c] * inv - mean * mean;
        float sc = __ldg(gamma + c) * rsqrtf((float)var + 1e-5f);
        sP[c] = sc;
        sP[C + c] = __ldg(beta + c) - (float)mean * sc;
    }
}

// flush register stats (C channels of s,q) to global double slot via smem racc[36]
__device__ __forceinline__ void stats_flush(const float* s, const float* q, int C,
                                            double* st, float* racc) {
    int lane = threadIdx.x & 31;
    for (int c = 0; c < C; c++) {
        float ss = warp_sum(s[c]);
        float qq = warp_sum(q[c]);
        if (lane == 0) { atomicAdd(&racc[c], ss); atomicAdd(&racc[18 + c], qq); }
    }
    __syncthreads();
    int t = threadIdx.x;
    if (t < C) atomicAdd(&st[t], (double)racc[t]);
    if (t >= 18 && t < 18 + C) atomicAdd(&st[t], (double)racc[t]);
}

// ---------------- kernels ----------------
__global__ void __launch_bounds__(256) k_init() {
    int i = blockIdx.x * 256 + threadIdx.x;
    if (i < GG * PS) { g_vn[i] = 0.f; g_gs[i] = 0.f; }
    if (i < 108) { g_stZ1[i] = 0.0; g_stZ2[i] = 0.0; }
    if (i < 72)  { g_stV1[i] = 0.0; g_stV2[i] = 0.0; }
    if (i < 9)   g_outacc[i] = 0.0;
}

// pack edge attrs: code = a0 + 6*a1 + 36*a2  (< 216), 1 byte per edge (run once)
__global__ void __launch_bounds__(256) k_pack(const int* __restrict__ ea) {
    int e = blockIdx.x * 256 + threadIdx.x;   // grid exactly covers EE
    int a0 = __ldg(ea + (size_t)3 * e);
    int a1 = __ldg(ea + (size_t)3 * e + 1);
    int a2 = __ldg(ea + (size_t)3 * e + 2);
    g_eb[e] = (unsigned char)(a0 + 6 * a1 + 36 * a2);
}

// build combined bond table for layer: g_bt[code*12+k] = b0[a0][k]+b1[a1][k]+b2[a2][k]
__global__ void k_btab(const float* __restrict__ bond) {
    for (int i = threadIdx.x; i < 216 * 12; i += 256) {
        int code = i / 12, k = i % 12;
        float v = 0.f;
        if (k < 9) {
            int a0 = code % 6, a1 = (code / 6) % 6, a2 = code / 36;
            v = __ldg(bond + a0 * 9 + k) + __ldg(bond + 54 + a1 * 9 + k)
              + __ldg(bond + 108 + a2 * 9 + k);
        }
        g_bt[i] = v;
    }
}

// AtomEncoder: h_in = sum_f atom_emb[f, x[n,f]]; zero msg buffer; graph sums of h_in
__global__ void __launch_bounds__(256) k_atom(const float* __restrict__ atom_emb,
                                              const int* __restrict__ x,
                                              const int* __restrict__ batch) {
    int n = blockIdx.x * 256 + threadIdx.x;   // grid exactly covers NN
    float h[9];
    #pragma unroll
    for (int k = 0; k < 9; k++) h[k] = 0.f;
    #pragma unroll
    for (int f = 0; f < 9; f++) {
        int v = __ldg(x + (size_t)n * 9 + f);
        const float* row = atom_emb + ((size_t)f * 119 + v) * 9;
        #pragma unroll
        for (int k = 0; k < 9; k++) h[k] += __ldg(row + k);
    }
    float4* hp = (float4*)(g_hin + (size_t)n * PS);
    hp[0] = make_float4(h[0], h[1], h[2], h[3]);
    hp[1] = make_float4(h[4], h[5], h[6], h[7]);
    hp[2] = make_float4(h[8], 0.f, 0.f, 0.f);
    float4 zz = make_float4(0.f, 0.f, 0.f, 0.f);
    float4* bp = (float4*)(g_buf + (size_t)n * PS);
    bp[0] = zz; bp[1] = zz; bp[2] = zz;
    int g = __ldg(batch + n);
    seg_atomic9(g, h, g_gs);
}

// GIN message: relu(h_in[src] + g_bt[code]) scatter-added at dst.
// Table read directly from global (10KB, L1-resident): no smem prologue, no divides.
__global__ void __launch_bounds__(256) k_edge(const int* __restrict__ src,
                                              const int* __restrict__ dst) {
    int e = blockIdx.x * 256 + threadIdx.x;   // grid exactly covers EE
    int s = __ldg(src + e);
    int d = __ldg(dst + e);
    int code = (int)g_eb[e];
    const float4* hp = (const float4*)(g_hin + (size_t)s * PS);
    float4 h0 = hp[0], h1 = hp[1], h2 = hp[2];
    const float4* tp = (const float4*)(g_bt + code * 12);
    float4 t0 = __ldg(tp), t1 = __ldg(tp + 1), t2 = __ldg(tp + 2);
    float m0 = fmaxf(h0.x + t0.x, 0.f), m1 = fmaxf(h0.y + t0.y, 0.f);
    float m2 = fmaxf(h0.z + t0.z, 0.f), m3 = fmaxf(h0.w + t0.w, 0.f);
    float m4 = fmaxf(h1.x + t1.x, 0.f), m5 = fmaxf(h1.y + t1.y, 0.f);
    float m6 = fmaxf(h1.z + t1.z, 0.f), m7 = fmaxf(h1.w + t1.w, 0.f);
    float m8 = fmaxf(h2.x + t2.x, 0.f);
    float* p = g_buf + (size_t)d * PS;
    red_add4(p,     m0, m1, m2, m3);
    red_add4(p + 4, m4, m5, m6, m7);
    red_add1(p + 8, m8);
}

// z = (1+eps)*h_in + aggr ; write z ; register stats of z@W1+b1 (18 ch)
// R6-proven form: NZI=8 fully unrolled, no reg cap (47.8us measured)
__global__ void __launch_bounds__(256) k_nodeZ(const float* __restrict__ W1,
                                               const float* __restrict__ b1,
                                               const float* __restrict__ eps_ptr, int l) {
    __shared__ float sW[162], sb[18], racc[36];
    int t = threadIdx.x;
    if (t < 162) sW[t] = W1[t];
    if (t < 18)  sb[t] = b1[t];
    if (t < 36)  racc[t] = 0.f;
    __syncthreads();
    float eps1 = 1.f + __ldg(eps_ptr);
    float s[18], q[18];
    #pragma unroll
    for (int c = 0; c < 18; c++) { s[c] = 0.f; q[c] = 0.f; }
    int base = blockIdx.x * (256 * NZI) + t;
    #pragma unroll
    for (int i = 0; i < NZI; i++) {
        int n = base + i * 256;
        float4* bp = (float4*)(g_buf + (size_t)n * PS);
        const float4* hp = (const float4*)(g_hin + (size_t)n * PS);
        float4 a = bp[0], b4 = bp[1], c4 = bp[2];
        float4 ha = hp[0], hb = hp[1], hc = hp[2];
        float z[9];
        z[0] = fmaf(eps1, ha.x, a.x);  z[1] = fmaf(eps1, ha.y, a.y);
        z[2] = fmaf(eps1, ha.z, a.z);  z[3] = fmaf(eps1, ha.w, a.w);
        z[4] = fmaf(eps1, hb.x, b4.x); z[5] = fmaf(eps1, hb.y, b4.y);
        z[6] = fmaf(eps1, hb.z, b4.z); z[7] = fmaf(eps1, hb.w, b4.w);
        z[8] = fmaf(eps1, hc.x, c4.x);
        bp[0] = make_float4(z[0], z[1], z[2], z[3]);
        bp[1] = make_float4(z[4], z[5], z[6], z[7]);
        bp[2] = make_float4(z[8], 0.f, 0.f, 0.f);
        #pragma unroll
        for (int c = 0; c < 18; c++) {
            float z1 = sb[c];
            #pragma unroll
            for (int j = 0; j < 9; j++) z1 = fmaf(z[j], sW[j * 18 + c], z1);
            s[c] += z1;
            q[c] = fmaf(z1, z1, q[c]);
        }
    }
    stats_flush(s, q, 18, g_stZ1 + l * 36, racc);
}

// y = relu(BN1(z@W1+b1)) (inline params); z2 = y@W2+b2; write z2; per-node stats of z2
// R5-proven per-node form (32-reg class, high occupancy)
__global__ void __launch_bounds__(256) k_nodeY(const float* __restrict__ W1,
                                               const float* __restrict__ b1,
                                               const float* __restrict__ W2,
                                               const float* __restrict__ b2,
                                               const float* __restrict__ bn1_g,
                                               const float* __restrict__ bn1_b, int l) {
    __shared__ float sW1[162], sW2[162], sb1[18], sb2[9], sP[36], racc[36];
    int t = threadIdx.x;
    if (t < 162) { sW1[t] = W1[t]; sW2[t] = W2[t]; }
    if (t < 18) sb1[t] = b1[t];
    if (t < 9)  sb2[t] = b2[t];
    if (t < 36) racc[t] = 0.f;
    compute_bn(g_stZ1 + l * 36, 18, 1.0 / (double)NN, bn1_g, bn1_b, sP);
    __syncthreads();
    int n = blockIdx.x * 256 + t;   // grid exactly covers NN
    float4* bp = (float4*)(g_buf + (size_t)n * PS);
    float4 a = bp[0], b4 = bp[1], c4 = bp[2];
    float z[9] = {a.x, a.y, a.z, a.w, b4.x, b4.y, b4.z, b4.w, c4.x};
    float z2[9];
    #pragma unroll
    for (int c = 0; c < 9; c++) z2[c] = sb2[c];
    #pragma unroll
    for (int c = 0; c < 18; c++) {
        float z1 = sb1[c];
        #pragma unroll
        for (int j = 0; j < 9; j++) z1 = fmaf(z[j], sW1[j * 18 + c], z1);
        float y = fmaxf(fmaf(z1, sP[c], sP[18 + c]), 0.f);
        #pragma unroll
        for (int j = 0; j < 9; j++) z2[j] = fmaf(y, sW2[c * 9 + j], z2[j]);
    }
    bp[0] = make_float4(z2[0], z2[1], z2[2], z2[3]);
    bp[1] = make_float4(z2[4], z2[5], z2[6], z2[7]);
    bp[2] = make_float4(z2[8], 0.f, 0.f, 0.f);
    int lane = t & 31;
    #pragma unroll
    for (int c = 0; c < 9; c++) {
        float ss = warp_sum(z2[c]);
        float qq = warp_sum(z2[c] * z2[c]);
        if (lane == 0) { atomicAdd(&racc[c], ss); atomicAdd(&racc[18 + c], qq); }
    }
    __syncthreads();
    double* st = g_stZ2 + l * 36;
    if (t < 9) atomicAdd(&st[t], (double)racc[t]);
    if (t >= 18 && t < 27) atomicAdd(&st[t], (double)racc[t]);
}

// VN step A: vn_tmp = graphsum + vn (stored back into g_gs); stats of vn_tmp@vnW1+vnb1
__global__ void __launch_bounds__(256) k_vnA(const float* __restrict__ W1,
                                             const float* __restrict__ b1, int l) {
    __shared__ float sW[162], sb[18], racc[36];
    int t = threadIdx.x;
    if (t < 162) sW[t] = W1[t];
    if (t < 18)  sb[t] = b1[t];
    if (t < 36)  racc[t] = 0.f;
    __syncthreads();
    int g = blockIdx.x * 256 + t;
    float4* gp = (float4*)(g_gs + (size_t)g * PS);
    const float4* vp = (const float4*)(g_vn + (size_t)g * PS);
    float4 a = gp[0], b4 = gp[1], c4 = gp[2];
    float4 va = vp[0], vb = vp[1], vc = vp[2];
    float vt[9] = {a.x + va.x, a.y + va.y, a.z + va.z, a.w + va.w,
                   b4.x + vb.x, b4.y + vb.y, b4.z + vb.z, b4.w + vb.w, c4.x + vc.x};
    gp[0] = make_float4(vt[0], vt[1], vt[2], vt[3]);
    gp[1] = make_float4(vt[4], vt[5], vt[6], vt[7]);
    gp[2] = make_float4(vt[8], 0.f, 0.f, 0.f);
    float s[18], q[18];
    #pragma unroll
    for (int c = 0; c < 18; c++) {
        float u = sb[c];
        #pragma unroll
        for (int j = 0; j < 9; j++) u = fmaf(vt[j], sW[j * 18 + c], u);
        s[c] = u; q[c] = u * u;
    }
    stats_flush(s, q, 18, g_stV1 + l * 36, racc);
}

// VN step B: t = relu(BN1(u1)) (inline params); u2 = t@vnW2+vnb2 -> g_gs; stats of u2
__global__ void __launch_bounds__(256) k_vnB(const float* __restrict__ W1,
                                             const float* __restrict__ b1,
                                             const float* __restrict__ W2,
                                             const float* __restrict__ b2,
                                             const float* __restrict__ bn_g,
                                             const float* __restrict__ bn_b, int l) {
    __shared__ float sW1[162], sW2[162], sb1[18], sb2[9], sP[36], racc[36];
    int t = threadIdx.x;
    if (t < 162) { sW1[t] = W1[t]; sW2[t] = W2[t]; }
    if (t < 18) sb1[t] = b1[t];
    if (t < 9)  sb2[t] = b2[t];
    if (t < 36) racc[t] = 0.f;
    compute_bn(g_stV1 + l * 36, 18, 1.0 / (double)GG, bn_g, bn_b, sP);
    __syncthreads();
    int g = blockIdx.x * 256 + t;
    float4* gp = (float4*)(g_gs + (size_t)g * PS);
    float4 a = gp[0], b4 = gp[1], c4 = gp[2];
    float vt[9] = {a.x, a.y, a.z, a.w, b4.x, b4.y, b4.z, b4.w, c4.x};
    float u2[9];
    #pragma unroll
    for (int c = 0; c < 9; c++) u2[c] = sb2[c];
    #pragma unroll
    for (int c = 0; c < 18; c++) {
        float u = sb1[c];
        #pragma unroll
        for (int j = 0; j < 9; j++) u = fmaf(vt[j], sW1[j * 18 + c], u);
        float y = fmaxf(fmaf(u, sP[c], sP[18 + c]), 0.f);
        #pragma unroll
        for (int j = 0; j < 9; j++) u2[j] = fmaf(y, sW2[c * 9 + j], u2[j]);
    }
    gp[0] = make_float4(u2[0], u2[1], u2[2], u2[3]);
    gp[1] = make_float4(u2[4], u2[5], u2[6], u2[7]);
    gp[2] = make_float4(u2[8], 0.f, 0.f, 0.f);
    float s[9], q[9];
    #pragma unroll
    for (int c = 0; c < 9; c++) { s[c] = u2[c]; q[c] = u2[c] * u2[c]; }
    stats_flush(s, q, 9, g_stV2 + l * 36, racc);
}

// VN step C: vn += relu(BN2(u2)) (inline params); zero graph-sum buffer for next layer
__global__ void __launch_bounds__(256) k_vnC(const float* __restrict__ bn_g,
                                             const float* __restrict__ bn_b, int l) {
    __shared__ float sP[18];
    compute_bn(g_stV2 + l * 36, 9, 1.0 / (double)GG, bn_g, bn_b, sP);
    __syncthreads();
    int g = blockIdx.x * 256 + threadIdx.x;
    float4* gp = (float4*)(g_gs + (size_t)g * PS);
    float4* vp = (float4*)(g_vn + (size_t)g * PS);
    float4 a = gp[0], b4 = gp[1], c4 = gp[2];
    float u2[9] = {a.x, a.y, a.z, a.w, b4.x, b4.y, b4.z, b4.w, c4.x};
    float4 va = vp[0], vb = vp[1], vc = vp[2];
    float vo[9] = {va.x, va.y, va.z, va.w, vb.x, vb.y, vb.z, vb.w, vc.x};
    #pragma unroll
    for (int k = 0; k < 9; k++)
        vo[k] += fmaxf(fmaf(u2[k], sP[k], sP[9 + k]), 0.f);
    vp[0] = make_float4(vo[0], vo[1], vo[2], vo[3]);
    vp[1] = make_float4(vo[4], vo[5], vo[6], vo[7]);
    vp[2] = make_float4(vo[8], 0.f, 0.f, 0.f);
    float4 zz = make_float4(0.f, 0.f, 0.f, 0.f);
    gp[0] = zz; gp[1] = zz; gp[2] = zz;
}

// layer finish (l<2): h_new = relu(BNout(z2)) + h_in (inline params); h_in' = h_new + vn'[batch]
__global__ void __launch_bounds__(256) k_final_mid(const int* __restrict__ batch,
                                                   const float* __restrict__ bn_g,
                                                   const float* __restrict__ bn_b,
                                                   int l, int accumGS) {
    __shared__ float sP[18];
    compute_bn(g_stZ2 + l * 36, 9, 1.0 / (double)NN, bn_g, bn_b, sP);
    __syncthreads();
    int n = blockIdx.x * 256 + threadIdx.x;   // grid exactly covers NN
    float4* bp = (float4*)(g_buf + (size_t)n * PS);
    float4* hp = (float4*)(g_hin + (size_t)n * PS);
    float4 a = bp[0], b4 = bp[1], c4 = bp[2];
    float z2[9] = {a.x, a.y, a.z, a.w, b4.x, b4.y, b4.z, b4.w, c4.x};
    float4 ha = hp[0], hb = hp[1], hc = hp[2];
    float hi[9] = {ha.x, ha.y, ha.z, ha.w, hb.x, hb.y, hb.z, hb.w, hc.x};
    int g = __ldg(batch + n);
    const float4* vp = (const float4*)(g_vn + (size_t)g * PS);
    float4 va = vp[0], vb = vp[1], vc = vp[2];
    float vn9[9] = {va.x, va.y, va.z, va.w, vb.x, vb.y, vb.z, vb.w, vc.x};
    float hx[9];
    #pragma unroll
    for (int k = 0; k < 9; k++) {
        float zn = fmaxf(fmaf(z2[k], sP[k], sP[9 + k]), 0.f);
        hx[k] = zn + hi[k] + vn9[k];
    }
    hp[0] = make_float4(hx[0], hx[1], hx[2], hx[3]);
    hp[1] = make_float4(hx[4], hx[5], hx[6], hx[7]);
    hp[2] = make_float4(hx[8], 0.f, 0.f, 0.f);
    float4 zz = make_float4(0.f, 0.f, 0.f, 0.f);
    bp[0] = zz; bp[1] = zz; bp[2] = zz;
    if (accumGS) seg_atomic9(g, hx, g_gs);
}

// last layer finish: h = BNout(z2) + h_in (no relu, inline params); global sum
__global__ void __launch_bounds__(256) k_final_last(const float* __restrict__ bn_g,
                                                    const float* __restrict__ bn_b, int l) {
    __shared__ float sP[18], racc[9];
    compute_bn(g_stZ2 + l * 36, 9, 1.0 / (double)NN, bn_g, bn_b, sP);
    if (threadIdx.x < 9) racc[threadIdx.x] = 0.f;
    __syncthreads();
    int n = blockIdx.x * 256 + threadIdx.x;   // grid exactly covers NN
    const float4* bp = (const float4*)(g_buf + (size_t)n * PS);
    const float4* hp = (const float4*)(g_hin + (size_t)n * PS);
    float4 a = bp[0], b4 = bp[1], c4 = bp[2];
    float z2[9] = {a.x, a.y, a.z, a.w, b4.x, b4.y, b4.z, b4.w, c4.x};
    float4 ha = hp[0], hb = hp[1], hc = hp[2];
    float hi[9] = {ha.x, ha.y, ha.z, ha.w, hb.x, hb.y, hb.z, hb.w, hc.x};
    int lane = threadIdx.x & 31;
    #pragma unroll
    for (int k = 0; k < 9; k++) {
        float h = fmaf(z2[k], sP[k], sP[9 + k]) + hi[k];
        float v = warp_sum(h);
        if (lane == 0) atomicAdd(&racc[k], v);
    }
    __syncthreads();
    if (threadIdx.x < 9) atomicAdd(&g_outacc[threadIdx.x], (double)racc[threadIdx.x]);
}

__global__ void k_out(float* __restrict__ out) {
    if (threadIdx.x < 9) out[threadIdx.x] = (float)g_outacc[threadIdx.x];
}

// ---------------- host ----------------
extern "C" void kernel_launch(void* const* d_in, const int* in_sizes, int n_in,
                              void* d_out, int out_size) {
    const float* atom_emb = (const float*)d_in[0];
    const float* bond_emb = (const float*)d_in[1];
    const float* eps_gin  = (const float*)d_in[2];
    const float* W1       = (const float*)d_in[3];
    const float* b1       = (const float*)d_in[4];
    const float* bn1_g    = (const float*)d_in[5];
    const float* bn1_b    = (const float*)d_in[6];
    const float* W2       = (const float*)d_in[7];
    const float* b2       = (const float*)d_in[8];
    const float* bno_g    = (const float*)d_in[9];
    const float* bno_b    = (const float*)d_in[10];
    const float* vnW1     = (const float*)d_in[11];
    const float* vnb1     = (const float*)d_in[12];
    const float* vnbn1_g  = (const float*)d_in[13];
    const float* vnbn1_b  = (const float*)d_in[14];
    const float* vnW2     = (const float*)d_in[15];
    const float* vnb2     = (const float*)d_in[16];
    const float* vnbn2_g  = (const float*)d_in[17];
    const float* vnbn2_b  = (const float*)d_in[18];
    const int*   x        = (const int*)d_in[19];
    const int*   eidx     = (const int*)d_in[20];
    const int*   eattr    = (const int*)d_in[21];
    const int*   batch    = (const int*)d_in[22];
    (void)in_sizes; (void)n_in; (void)out_size;

    k_init<<<(GG * PS + 255) / 256, 256>>>();
    k_pack<<<NB_E, 256>>>(eattr);
    k_atom<<<NB_N, 256>>>(atom_emb, x, batch);

    for (int l = 0; l < 3; l++) {
        k_btab<<<1, 256>>>(bond_emb + l * 162);
        k_edge<<<NB_E, 256>>>(eidx, eidx + EE);
        k_nodeZ<<<NB_Z, 256>>>(W1 + l * 162, b1 + l * 18, eps_gin + l, l);
        k_nodeY<<<NB_N, 256>>>(W1 + l * 162, b1 + l * 18, W2 + l * 162, b2 + l * 9,
                               bn1_g + l * 18, bn1_b + l * 18, l);
        if (l < 2) {
            k_vnA<<<NB_G, 256>>>(vnW1 + l * 162, vnb1 + l * 18, l);
            k_vnB<<<NB_G, 256>>>(vnW1 + l * 162, vnb1 + l * 18, vnW2 + l * 162,
                                 vnb2 + l * 9, vnbn1_g + l * 18, vnbn1_b + l * 18, l);
            k_vnC<<<NB_G, 256>>>(vnbn2_g + l * 9, vnbn2_b + l * 9, l);
            k_final_mid<<<NB_N, 256>>>(batch, bno_g + l * 9, bno_b + l * 9, l,
                                       (l == 0) ? 1 : 0);
        } else {
            k_final_last<<<NB_N, 256>>>(bno_g + l * 9, bno_b + l * 9, l);
        }
    }
    k_out<<<1, 32>>>((float*)d_out);
}

// round 12
// speedup vs baseline: 2.3937x; 1.0953x over previous
#include <cuda_runtime.h>
#include <cuda_fp16.h>

#define NN 1048576
#define EE 8388608
#define GG 32768
#define PS 12   // fp32 row stride (9 ch + 3 pad) -> 48B
#define HS 16   // fp16 shadow row stride in halves -> 32B, 32B-aligned (1 sector)
#define NZI 8                           // nodes/thread in k_nodeZ (R6-proven full unroll)
#define NB_Z (NN / (256 * NZI))         // 512
#define NB_N (NN / 256)                 // 4096
#define NB_E (EE / 256)                 // 32768
#define NB_G (GG / 256)                 // 128

// ---------------- device state (no allocation allowed) ----------------
__device__ __align__(16) float  g_hin[(size_t)NN * PS];
__device__ __align__(32) __half g_h16[(size_t)NN * HS];   // fp16 shadow of h_in (32MB)
__device__ __align__(16) float  g_buf[(size_t)NN * PS];
__device__ __align__(16) float  g_vn [(size_t)GG * PS];
__device__ __align__(16) float  g_gs [(size_t)GG * PS];
__device__ unsigned char g_eb[(size_t)EE];           // packed edge attr codes (<216)
__device__ __align__(16) float g_bt[3 * 216 * 12];   // combined bond tables, all layers
// per-layer raw BN stats: sum at [c], sumsq at [18+c], 36-stride per layer
__device__ double g_stZ1[3 * 36];
__device__ double g_stZ2[3 * 36];
__device__ double g_stV1[2 * 36];
__device__ double g_stV2[2 * 36];
__device__ double g_outacc[9];

// ---------------- helpers ----------------
__device__ __forceinline__ void red_add4(float* p, float a, float b, float c, float d) {
    asm volatile("red.global.add.v4.f32 [%0], {%1,%2,%3,%4};"
                 :: "l"(__cvta_generic_to_global(p)), "f"(a), "f"(b), "f"(c), "f"(d) : "memory");
}
__device__ __forceinline__ void red_add1(float* p, float a) {
    asm volatile("red.global.add.f32 [%0], %1;"
                 :: "l"(__cvta_generic_to_global(p)), "f"(a) : "memory");
}
__device__ __forceinline__ float warp_sum(float v) {
    #pragma unroll
    for (int off = 16; off > 0; off >>= 1) v += __shfl_down_sync(0xffffffffu, v, off);
    return v;
}

// store 9 floats as fp16 shadow row (two 16B stores, 32B-aligned row)
__device__ __forceinline__ void store_h16(int n, const float* h) {
    __half2 hh[8];
    hh[0] = __floats2half2_rn(h[0], h[1]);
    hh[1] = __floats2half2_rn(h[2], h[3]);
    hh[2] = __floats2half2_rn(h[4], h[5]);
    hh[3] = __floats2half2_rn(h[6], h[7]);
    hh[4] = __floats2half2_rn(h[8], 0.f);
    hh[5] = hh[6] = hh[7] = __floats2half2_rn(0.f, 0.f);
    uint4* sp = (uint4*)(g_h16 + (size_t)n * HS);
    sp[0] = *(uint4*)&hh[0];
    sp[1] = *(uint4*)&hh[4];
}

// warp-level segmented sum over sorted keys, then 3 vector atomics per segment head
__device__ __forceinline__ void seg_atomic9(int key, float v[9], float* dstBase) {
    int lane = threadIdx.x & 31;
    #pragma unroll
    for (int off = 1; off < 32; off <<= 1) {
        int nk = __shfl_down_sync(0xffffffffu, key, off);
        float t[9];
        #pragma unroll
        for (int k = 0; k < 9; k++) t[k] = __shfl_down_sync(0xffffffffu, v[k], off);
        if (lane + off < 32 && nk == key) {
            #pragma unroll
            for (int k = 0; k < 9; k++) v[k] += t[k];
        }
    }
    int pk = __shfl_up_sync(0xffffffffu, key, 1);
    if (lane == 0 || pk != key) {
        float* p = dstBase + (size_t)key * PS;
        red_add4(p,     v[0], v[1], v[2], v[3]);
        red_add4(p + 4, v[4], v[5], v[6], v[7]);
        red_add1(p + 8, v[8]);
    }
}

// inline BN param computation: threads c<C write sP[c]=scale, sP[C+c]=shift.
__device__ __forceinline__ void compute_bn(const double* st, int C, double inv,
                                           const float* gamma, const float* beta,
                                           float* sP) {
    int c = threadIdx.x;
    if (c < C) {
        double mean = st[c] * inv;
        double var  = st[18 + c] * inv - mean * mean;
        float sc = __ldg(gamma + c) * rsqrtf((float)var + 1e-5f);
        sP[c] = sc;
        sP[C + c] = __ldg(beta + c) - (float)mean * sc;
    }
}

// flush register stats (C channels of s,q) to global double slot via smem racc[36]
__device__ __forceinline__ void stats_flush(const float* s, const float* q, int C,
                                            double* st, float* racc) {
    int lane = threadIdx.x & 31;
    for (int c = 0; c < C; c++) {
        float ss = warp_sum(s[c]);
        float qq = warp_sum(q[c]);
        if (lane == 0) { atomicAdd(&racc[c], ss); atomicAdd(&racc[18 + c], qq); }
    }
    __syncthreads();
    int t = threadIdx.x;
    if (t < C) atomicAdd(&st[t], (double)racc[t]);
    if (t >= 18 && t < 18 + C) atomicAdd(&st[t], (double)racc[t]);
}

// ---------------- kernels ----------------
__global__ void __launch_bounds__(256) k_init() {
    int i = blockIdx.x * 256 + threadIdx.x;
    if (i < GG * PS) { g_vn[i] = 0.f; g_gs[i] = 0.f; }
    if (i < 108) { g_stZ1[i] = 0.0; g_stZ2[i] = 0.0; }
    if (i < 72)  { g_stV1[i] = 0.0; g_stV2[i] = 0.0; }
    if (i < 9)   g_outacc[i] = 0.0;
}

// pack edge attrs: code = a0 + 6*a1 + 36*a2  (< 216), 1 byte per edge (run once)
__global__ void __launch_bounds__(256) k_pack(const int* __restrict__ ea) {
    int e = blockIdx.x * 256 + threadIdx.x;
    int a0 = __ldg(ea + (size_t)3 * e);
    int a1 = __ldg(ea + (size_t)3 * e + 1);
    int a2 = __ldg(ea + (size_t)3 * e + 2);
    g_eb[e] = (unsigned char)(a0 + 6 * a1 + 36 * a2);
}

// build combined bond tables for ALL 3 layers (one launch, 3 blocks)
__global__ void k_btab3(const float* __restrict__ bond_all) {
    const float* bond = bond_all + blockIdx.x * 162;
    float* bt = g_bt + blockIdx.x * (216 * 12);
    for (int i = threadIdx.x; i < 216 * 12; i += 256) {
        int code = i / 12, k = i % 12;
        float v = 0.f;
        if (k < 9) {
            int a0 = code % 6, a1 = (code / 6) % 6, a2 = code / 36;
            v = __ldg(bond + a0 * 9 + k) + __ldg(bond + 54 + a1 * 9 + k)
              + __ldg(bond + 108 + a2 * 9 + k);
        }
        bt[i] = v;
    }
}

// AtomEncoder: h_in = sum_f atom_emb[f, x[n,f]]; fp16 shadow; zero msg buffer; graph sums
__global__ void __launch_bounds__(256) k_atom(const float* __restrict__ atom_emb,
                                              const int* __restrict__ x,
                                              const int* __restrict__ batch) {
    int n = blockIdx.x * 256 + threadIdx.x;
    float h[9];
    #pragma unroll
    for (int k = 0; k < 9; k++) h[k] = 0.f;
    #pragma unroll
    for (int f = 0; f < 9; f++) {
        int v = __ldg(x + (size_t)n * 9 + f);
        const float* row = atom_emb + ((size_t)f * 119 + v) * 9;
        #pragma unroll
        for (int k = 0; k < 9; k++) h[k] += __ldg(row + k);
    }
    float4* hp = (float4*)(g_hin + (size_t)n * PS);
    hp[0] = make_float4(h[0], h[1], h[2], h[3]);
    hp[1] = make_float4(h[4], h[5], h[6], h[7]);
    hp[2] = make_float4(h[8], 0.f, 0.f, 0.f);
    store_h16(n, h);
    float4 zz = make_float4(0.f, 0.f, 0.f, 0.f);
    float4* bp = (float4*)(g_buf + (size_t)n * PS);
    bp[0] = zz; bp[1] = zz; bp[2] = zz;
    int g = __ldg(batch + n);
    seg_atomic9(g, h, g_gs);
}

// GIN message: relu(h16[src] + g_bt[l][code]) scatter-added at dst.
// fp16 gather = exactly ONE 32B sector per edge.
__global__ void __launch_bounds__(256) k_edge(const int* __restrict__ src,
                                              const int* __restrict__ dst, int l) {
    const float* bt = g_bt + l * (216 * 12);
    int e = blockIdx.x * 256 + threadIdx.x;
    int s = __ldg(src + e);
    int d = __ldg(dst + e);
    int code = (int)g_eb[e];
    const uint4* hp = (const uint4*)(g_h16 + (size_t)s * HS);
    uint4 u0 = __ldg(hp);                                   // halves 0..7
    unsigned int u8 = __ldg((const unsigned int*)(hp + 1)); // halves 8,9
    float2 f0 = __half22float2(*(__half2*)&u0.x);
    float2 f1 = __half22float2(*(__half2*)&u0.y);
    float2 f2 = __half22float2(*(__half2*)&u0.z);
    float2 f3 = __half22float2(*(__half2*)&u0.w);
    float2 f4 = __half22float2(*(__half2*)&u8);
    const float4* tp = (const float4*)(bt + code * 12);
    float4 t0 = __ldg(tp), t1 = __ldg(tp + 1), t2 = __ldg(tp + 2);
    float m0 = fmaxf(f0.x + t0.x, 0.f), m1 = fmaxf(f0.y + t0.y, 0.f);
    float m2 = fmaxf(f1.x + t0.z, 0.f), m3 = fmaxf(f1.y + t0.w, 0.f);
    float m4 = fmaxf(f2.x + t1.x, 0.f), m5 = fmaxf(f2.y + t1.y, 0.f);
    float m6 = fmaxf(f3.x + t1.z, 0.f), m7 = fmaxf(f3.y + t1.w, 0.f);
    float m8 = fmaxf(f4.x + t2.x, 0.f);
    float* p = g_buf + (size_t)d * PS;
    red_add4(p,     m0, m1, m2, m3);
    red_add4(p + 4, m4, m5, m6, m7);
    red_add1(p + 8, m8);
}

// z = (1+eps)*h_in + aggr ; write z ; register stats of z@W1+b1 (18 ch)
// R6-proven form: NZI=8 fully unrolled, no reg cap (47.8us measured)
__global__ void __launch_bounds__(256) k_nodeZ(const float* __restrict__ W1,
                                               const float* __restrict__ b1,
                                               const float* __restrict__ eps_ptr, int l) {
    __shared__ float sW[162], sb[18], racc[36];
    int t = threadIdx.x;
    if (t < 162) sW[t] = W1[t];
    if (t < 18)  sb[t] = b1[t];
    if (t < 36)  racc[t] = 0.f;
    __syncthreads();
    float eps1 = 1.f + __ldg(eps_ptr);
    float s[18], q[18];
    #pragma unroll
    for (int c = 0; c < 18; c++) { s[c] = 0.f; q[c] = 0.f; }
    int base = blockIdx.x * (256 * NZI) + t;
    #pragma unroll
    for (int i = 0; i < NZI; i++) {
        int n = base + i * 256;
        float4* bp = (float4*)(g_buf + (size_t)n * PS);
        const float4* hp = (const float4*)(g_hin + (size_t)n * PS);
        float4 a = bp[0], b4 = bp[1], c4 = bp[2];
        float4 ha = hp[0], hb = hp[1], hc = hp[2];
        float z[9];
        z[0] = fmaf(eps1, ha.x, a.x);  z[1] = fmaf(eps1, ha.y, a.y);
        z[2] = fmaf(eps1, ha.z, a.z);  z[3] = fmaf(eps1, ha.w, a.w);
        z[4] = fmaf(eps1, hb.x, b4.x); z[5] = fmaf(eps1, hb.y, b4.y);
        z[6] = fmaf(eps1, hb.z, b4.z); z[7] = fmaf(eps1, hb.w, b4.w);
        z[8] = fmaf(eps1, hc.x, c4.x);
        bp[0] = make_float4(z[0], z[1], z[2], z[3]);
        bp[1] = make_float4(z[4], z[5], z[6], z[7]);
        bp[2] = make_float4(z[8], 0.f, 0.f, 0.f);
        #pragma unroll
        for (int c = 0; c < 18; c++) {
            float z1 = sb[c];
            #pragma unroll
            for (int j = 0; j < 9; j++) z1 = fmaf(z[j], sW[j * 18 + c], z1);
            s[c] += z1;
            q[c] = fmaf(z1, z1, q[c]);
        }
    }
    stats_flush(s, q, 18, g_stZ1 + l * 36, racc);
}

// y = relu(BN1(z@W1+b1)) (inline params); z2 = y@W2+b2; write z2; per-node stats of z2
__global__ void __launch_bounds__(256) k_nodeY(const float* __restrict__ W1,
                                               const float* __restrict__ b1,
                                               const float* __restrict__ W2,
                                               const float* __restrict__ b2,
                                               const float* __restrict__ bn1_g,
                                               const float* __restrict__ bn1_b, int l) {
    __shared__ float sW1[162], sW2[162], sb1[18], sb2[9], sP[36], racc[36];
    int t = threadIdx.x;
    if (t < 162) { sW1[t] = W1[t]; sW2[t] = W2[t]; }
    if (t < 18) sb1[t] = b1[t];
    if (t < 9)  sb2[t] = b2[t];
    if (t < 36) racc[t] = 0.f;
    compute_bn(g_stZ1 + l * 36, 18, 1.0 / (double)NN, bn1_g, bn1_b, sP);
    __syncthreads();
    int n = blockIdx.x * 256 + t;
    float4* bp = (float4*)(g_buf + (size_t)n * PS);
    float4 a = bp[0], b4 = bp[1], c4 = bp[2];
    float z[9] = {a.x, a.y, a.z, a.w, b4.x, b4.y, b4.z, b4.w, c4.x};
    float z2[9];
    #pragma unroll
    for (int c = 0; c < 9; c++) z2[c] = sb2[c];
    #pragma unroll
    for (int c = 0; c < 18; c++) {
        float z1 = sb1[c];
        #pragma unroll
        for (int j = 0; j < 9; j++) z1 = fmaf(z[j], sW1[j * 18 + c], z1);
        float y = fmaxf(fmaf(z1, sP[c], sP[18 + c]), 0.f);
        #pragma unroll
        for (int j = 0; j < 9; j++) z2[j] = fmaf(y, sW2[c * 9 + j], z2[j]);
    }
    bp[0] = make_float4(z2[0], z2[1], z2[2], z2[3]);
    bp[1] = make_float4(z2[4], z2[5], z2[6], z2[7]);
    bp[2] = make_float4(z2[8], 0.f, 0.f, 0.f);
    int lane = t & 31;
    #pragma unroll
    for (int c = 0; c < 9; c++) {
        float ss = warp_sum(z2[c]);
        float qq = warp_sum(z2[c] * z2[c]);
        if (lane == 0) { atomicAdd(&racc[c], ss); atomicAdd(&racc[18 + c], qq); }
    }
    __syncthreads();
    double* st = g_stZ2 + l * 36;
    if (t < 9) atomicAdd(&st[t], (double)racc[t]);
    if (t >= 18 && t < 27) atomicAdd(&st[t], (double)racc[t]);
}

// VN step A
__global__ void __launch_bounds__(256) k_vnA(const float* __restrict__ W1,
                                             const float* __restrict__ b1, int l) {
    __shared__ float sW[162], sb[18], racc[36];
    int t = threadIdx.x;
    if (t < 162) sW[t] = W1[t];
    if (t < 18)  sb[t] = b1[t];
    if (t < 36)  racc[t] = 0.f;
    __syncthreads();
    int g = blockIdx.x * 256 + t;
    float4* gp = (float4*)(g_gs + (size_t)g * PS);
    const float4* vp = (const float4*)(g_vn + (size_t)g * PS);
    float4 a = gp[0], b4 = gp[1], c4 = gp[2];
    float4 va = vp[0], vb = vp[1], vc = vp[2];
    float vt[9] = {a.x + va.x, a.y + va.y, a.z + va.z, a.w + va.w,
                   b4.x + vb.x, b4.y + vb.y, b4.z + vb.z, b4.w + vb.w, c4.x + vc.x};
    gp[0] = make_float4(vt[0], vt[1], vt[2], vt[3]);
    gp[1] = make_float4(vt[4], vt[5], vt[6], vt[7]);
    gp[2] = make_float4(vt[8], 0.f, 0.f, 0.f);
    float s[18], q[18];
    #pragma unroll
    for (int c = 0; c < 18; c++) {
        float u = sb[c];
        #pragma unroll
        for (int j = 0; j < 9; j++) u = fmaf(vt[j], sW[j * 18 + c], u);
        s[c] = u; q[c] = u * u;
    }
    stats_flush(s, q, 18, g_stV1 + l * 36, racc);
}

// VN step B
__global__ void __launch_bounds__(256) k_vnB(const float* __restrict__ W1,
                                             const float* __restrict__ b1,
                                             const float* __restrict__ W2,
                                             const float* __restrict__ b2,
                                             const float* __restrict__ bn_g,
                                             const float* __restrict__ bn_b, int l) {
    __shared__ float sW1[162], sW2[162], sb1[18], sb2[9], sP[36], racc[36];
    int t = threadIdx.x;
    if (t < 162) { sW1[t] = W1[t]; sW2[t] = W2[t]; }
    if (t < 18) sb1[t] = b1[t];
    if (t < 9)  sb2[t] = b2[t];
    if (t < 36) racc[t] = 0.f;
    compute_bn(g_stV1 + l * 36, 18, 1.0 / (double)GG, bn_g, bn_b, sP);
    __syncthreads();
    int g = blockIdx.x * 256 + t;
    float4* gp = (float4*)(g_gs + (size_t)g * PS);
    float4 a = gp[0], b4 = gp[1], c4 = gp[2];
    float vt[9] = {a.x, a.y, a.z, a.w, b4.x, b4.y, b4.z, b4.w, c4.x};
    float u2[9];
    #pragma unroll
    for (int c = 0; c < 9; c++) u2[c] = sb2[c];
    #pragma unroll
    for (int c = 0; c < 18; c++) {
        float u = sb1[c];
        #pragma unroll
        for (int j = 0; j < 9; j++) u = fmaf(vt[j], sW1[j * 18 + c], u);
        float y = fmaxf(fmaf(u, sP[c], sP[18 + c]), 0.f);
        #pragma unroll
        for (int j = 0; j < 9; j++) u2[j] = fmaf(y, sW2[c * 9 + j], u2[j]);
    }
    gp[0] = make_float4(u2[0], u2[1], u2[2], u2[3]);
    gp[1] = make_float4(u2[4], u2[5], u2[6], u2[7]);
    gp[2] = make_float4(u2[8], 0.f, 0.f, 0.f);
    float s[9], q[9];
    #pragma unroll
    for (int c = 0; c < 9; c++) { s[c] = u2[c]; q[c] = u2[c] * u2[c]; }
    stats_flush(s, q, 9, g_stV2 + l * 36, racc);
}

// VN step C
__global__ void __launch_bounds__(256) k_vnC(const float* __restrict__ bn_g,
                                             const float* __restrict__ bn_b, int l) {
    __shared__ float sP[18];
    compute_bn(g_stV2 + l * 36, 9, 1.0 / (double)GG, bn_g, bn_b, sP);
    __syncthreads();
    int g = blockIdx.x * 256 + threadIdx.x;
    float4* gp = (float4*)(g_gs + (size_t)g * PS);
    float4* vp = (float4*)(g_vn + (size_t)g * PS);
    float4 a = gp[0], b4 = gp[1], c4 = gp[2];
    float u2[9] = {a.x, a.y, a.z, a.w, b4.x, b4.y, b4.z, b4.w, c4.x};
    float4 va = vp[0], vb = vp[1], vc = vp[2];
    float vo[9] = {va.x, va.y, va.z, va.w, vb.x, vb.y, vb.z, vb.w, vc.x};
    #pragma unroll
    for (int k = 0; k < 9; k++)
        vo[k] += fmaxf(fmaf(u2[k], sP[k], sP[9 + k]), 0.f);
    vp[0] = make_float4(vo[0], vo[1], vo[2], vo[3]);
    vp[1] = make_float4(vo[4], vo[5], vo[6], vo[7]);
    vp[2] = make_float4(vo[8], 0.f, 0.f, 0.f);
    float4 zz = make_float4(0.f, 0.f, 0.f, 0.f);
    gp[0] = zz; gp[1] = zz; gp[2] = zz;
}

// layer finish (l<2): h_new = relu(BNout(z2)) + h_in; h_in' = h_new + vn'[batch]; fp16 shadow
__global__ void __launch_bounds__(256) k_final_mid(const int* __restrict__ batch,
                                                   const float* __restrict__ bn_g,
                                                   const float* __restrict__ bn_b,
                                                   int l, int accumGS) {
    __shared__ float sP[18];
    compute_bn(g_stZ2 + l * 36, 9, 1.0 / (double)NN, bn_g, bn_b, sP);
    __syncthreads();
    int n = blockIdx.x * 256 + threadIdx.x;
    float4* bp = (float4*)(g_buf + (size_t)n * PS);
    float4* hp = (float4*)(g_hin + (size_t)n * PS);
    float4 a = bp[0], b4 = bp[1], c4 = bp[2];
    float z2[9] = {a.x, a.y, a.z, a.w, b4.x, b4.y, b4.z, b4.w, c4.x};
    float4 ha = hp[0], hb = hp[1], hc = hp[2];
    float hi[9] = {ha.x, ha.y, ha.z, ha.w, hb.x, hb.y, hb.z, hb.w, hc.x};
    int g = __ldg(batch + n);
    const float4* vp = (const float4*)(g_vn + (size_t)g * PS);
    float4 va = vp[0], vb = vp[1], vc = vp[2];
    float vn9[9] = {va.x, va.y, va.z, va.w, vb.x, vb.y, vb.z, vb.w, vc.x};
    float hx[9];
    #pragma unroll
    for (int k = 0; k < 9; k++) {
        float zn = fmaxf(fmaf(z2[k], sP[k], sP[9 + k]), 0.f);
        hx[k] = zn + hi[k] + vn9[k];
    }
    hp[0] = make_float4(hx[0], hx[1], hx[2], hx[3]);
    hp[1] = make_float4(hx[4], hx[5], hx[6], hx[7]);
    hp[2] = make_float4(hx[8], 0.f, 0.f, 0.f);
    store_h16(n, hx);
    float4 zz = make_float4(0.f, 0.f, 0.f, 0.f);
    bp[0] = zz; bp[1] = zz; bp[2] = zz;
    if (accumGS) seg_atomic9(g, hx, g_gs);
}

// last layer finish: h = BNout(z2) + h_in (no relu); global sum
__global__ void __launch_bounds__(256) k_final_last(const float* __restrict__ bn_g,
                                                    const float* __restrict__ bn_b, int l) {
    __shared__ float sP[18], racc[9];
    compute_bn(g_stZ2 + l * 36, 9, 1.0 / (double)NN, bn_g, bn_b, sP);
    if (threadIdx.x < 9) racc[threadIdx.x] = 0.f;
    __syncthreads();
    int n = blockIdx.x * 256 + threadIdx.x;
    const float4* bp = (const float4*)(g_buf + (size_t)n * PS);
    const float4* hp = (const float4*)(g_hin + (size_t)n * PS);
    float4 a = bp[0], b4 = bp[1], c4 = bp[2];
    float z2[9] = {a.x, a.y, a.z, a.w, b4.x, b4.y, b4.z, b4.w, c4.x};
    float4 ha = hp[0], hb = hp[1], hc = hp[2];
    float hi[9] = {ha.x, ha.y, ha.z, ha.w, hb.x, hb.y, hb.z, hb.w, hc.x};
    int lane = threadIdx.x & 31;
    #pragma unroll
    for (int k = 0; k < 9; k++) {
        float h = fmaf(z2[k], sP[k], sP[9 + k]) + hi[k];
        float v = warp_sum(h);
        if (lane == 0) atomicAdd(&racc[k], v);
    }
    __syncthreads();
    if (threadIdx.x < 9) atomicAdd(&g_outacc[threadIdx.x], (double)racc[threadIdx.x]);
}

__global__ void k_out(float* __restrict__ out) {
    if (threadIdx.x < 9) out[threadIdx.x] = (float)g_outacc[threadIdx.x];
}

// ---------------- host ----------------
extern "C" void kernel_launch(void* const* d_in, const int* in_sizes, int n_in,
                              void* d_out, int out_size) {
    const float* atom_emb = (const float*)d_in[0];
    const float* bond_emb = (const float*)d_in[1];
    const float* eps_gin  = (const float*)d_in[2];
    const float* W1       = (const float*)d_in[3];
    const float* b1       = (const float*)d_in[4];
    const float* bn1_g    = (const float*)d_in[5];
    const float* bn1_b    = (const float*)d_in[6];
    const float* W2       = (const float*)d_in[7];
    const float* b2       = (const float*)d_in[8];
    const float* bno_g    = (const float*)d_in[9];
    const float* bno_b    = (const float*)d_in[10];
    const float* vnW1     = (const float*)d_in[11];
    const float* vnb1     = (const float*)d_in[12];
    const float* vnbn1_g  = (const float*)d_in[13];
    const float* vnbn1_b  = (const float*)d_in[14];
    const float* vnW2     = (const float*)d_in[15];
    const float* vnb2     = (const float*)d_in[16];
    const float* vnbn2_g  = (const float*)d_in[17];
    const float* vnbn2_b  = (const float*)d_in[18];
    const int*   x        = (const int*)d_in[19];
    const int*   eidx     = (const int*)d_in[20];
    const int*   eattr    = (const int*)d_in[21];
    const int*   batch    = (const int*)d_in[22];
    (void)in_sizes; (void)n_in; (void)out_size;

    k_init<<<(GG * PS + 255) / 256, 256>>>();
    k_pack<<<NB_E, 256>>>(eattr);
    k_btab3<<<3, 256>>>(bond_emb);
    k_atom<<<NB_N, 256>>>(atom_emb, x, batch);

    for (int l = 0; l < 3; l++) {
        k_edge<<<NB_E, 256>>>(eidx, eidx + EE, l);
        k_nodeZ<<<NB_Z, 256>>>(W1 + l * 162, b1 + l * 18, eps_gin + l, l);
        k_nodeY<<<NB_N, 256>>>(W1 + l * 162, b1 + l * 18, W2 + l * 162, b2 + l * 9,
                               bn1_g + l * 18, bn1_b + l * 18, l);
        if (l < 2) {
            k_vnA<<<NB_G, 256>>>(vnW1 + l * 162, vnb1 + l * 18, l);
            k_vnB<<<NB_G, 256>>>(vnW1 + l * 162, vnb1 + l * 18, vnW2 + l * 162,
                                 vnb2 + l * 9, vnbn1_g + l * 18, vnbn1_b + l * 18, l);
            k_vnC<<<NB_G, 256>>>(vnbn2_g + l * 9, vnbn2_b + l * 9, l);
            k_final_mid<<<NB_N, 256>>>(batch, bno_g + l * 9, bno_b + l * 9, l,
                                       (l == 0) ? 1 : 0);
        } else {
            k_final_last<<<NB_N, 256>>>(bno_g + l * 9, bno_b + l * 9, l);
        }
    }
    k_out<<<1, 32>>>((float*)d_out);
}

// round 13
// speedup vs baseline: 2.6759x; 1.1179x over previous
#include <cuda_runtime.h>
#include <cuda_fp16.h>

#define NN 1048576
#define EE 8388608
#define GG 32768
#define PS 12   // fp32 row stride (9 ch + 3 pad) -> 48B
#define HS 16   // fp16 row stride in halves -> 32B (1 sector)
#define NZI 8                           // nodes/thread in k_nodeZ (R6-proven full unroll)
#define NB_Z (NN / (256 * NZI))         // 512
#define NB_N (NN / 256)                 // 4096
#define NB_E (EE / 256)                 // 32768
#define NB_G (GG / 256)                 // 128

// ---------------- device state (no allocation allowed) ----------------
__device__ __align__(16) float  g_hin[(size_t)NN * PS];
__device__ __align__(32) __half g_h16[(size_t)NN * HS];   // fp16 shadow of h_in (32MB)
__device__ __align__(32) __half g_ab [(size_t)NN * HS];   // fp16 edge-aggr accumulator (32MB)
__device__ __align__(16) float  g_buf[(size_t)NN * PS];   // z / z2 scratch (never zeroed)
__device__ __align__(16) float  g_vn [(size_t)GG * PS];
__device__ __align__(16) float  g_gs [(size_t)GG * PS];
__device__ unsigned char g_eb[(size_t)EE];           // packed edge attr codes (<216)
__device__ __align__(16) float g_bt[3 * 216 * 12];   // combined bond tables, all layers
// per-layer raw BN stats: sum at [c], sumsq at [18+c], 36-stride per layer
__device__ double g_stZ1[3 * 36];
__device__ double g_stZ2[3 * 36];
__device__ double g_stV1[2 * 36];
__device__ double g_stV2[2 * 36];
__device__ double g_outacc[9];

// ---------------- helpers ----------------
__device__ __forceinline__ void red_add4(float* p, float a, float b, float c, float d) {
    asm volatile("red.global.add.v4.f32 [%0], {%1,%2,%3,%4};"
                 :: "l"(__cvta_generic_to_global(p)), "f"(a), "f"(b), "f"(c), "f"(d) : "memory");
}
__device__ __forceinline__ void red_add1(float* p, float a) {
    asm volatile("red.global.add.f32 [%0], %1;"
                 :: "l"(__cvta_generic_to_global(p)), "f"(a) : "memory");
}
// fp16x2 vector reductions (sm_90+): 8 halves in one op, 2 halves in the scalar form
__device__ __forceinline__ void red_add_h2v4(__half* p, unsigned a, unsigned b,
                                             unsigned c, unsigned d) {
    asm volatile("red.global.add.noftz.v4.f16x2 [%0], {%1,%2,%3,%4};"
                 :: "l"(__cvta_generic_to_global(p)), "r"(a), "r"(b), "r"(c), "r"(d) : "memory");
}
__device__ __forceinline__ void red_add_h2(__half* p, unsigned a) {
    asm volatile("red.global.add.noftz.f16x2 [%0], %1;"
                 :: "l"(__cvta_generic_to_global(p)), "r"(a) : "memory");
}
__device__ __forceinline__ float warp_sum(float v) {
    #pragma unroll
    for (int off = 16; off > 0; off >>= 1) v += __shfl_down_sync(0xffffffffu, v, off);
    return v;
}

// store 9 floats as fp16 row (two 16B stores, 32B-aligned row)
__device__ __forceinline__ void store_h16(__half* basePtr, int n, const float* h) {
    __half2 hh[8];
    hh[0] = __floats2half2_rn(h[0], h[1]);
    hh[1] = __floats2half2_rn(h[2], h[3]);
    hh[2] = __floats2half2_rn(h[4], h[5]);
    hh[3] = __floats2half2_rn(h[6], h[7]);
    hh[4] = __floats2half2_rn(h[8], 0.f);
    hh[5] = hh[6] = hh[7] = __floats2half2_rn(0.f, 0.f);
    uint4* sp = (uint4*)(basePtr + (size_t)n * HS);
    sp[0] = *(uint4*)&hh[0];
    sp[1] = *(uint4*)&hh[4];
}
__device__ __forceinline__ void zero_h16(__half* basePtr, int n) {
    uint4 z = make_uint4(0u, 0u, 0u, 0u);
    uint4* sp = (uint4*)(basePtr + (size_t)n * HS);
    sp[0] = z; sp[1] = z;
}

// warp-level segmented sum over sorted keys, then 3 vector atomics per segment head
__device__ __forceinline__ void seg_atomic9(int key, float v[9], float* dstBase) {
    int lane = threadIdx.x & 31;
    #pragma unroll
    for (int off = 1; off < 32; off <<= 1) {
        int nk = __shfl_down_sync(0xffffffffu, key, off);
        float t[9];
        #pragma unroll
        for (int k = 0; k < 9; k++) t[k] = __shfl_down_sync(0xffffffffu, v[k], off);
        if (lane + off < 32 && nk == key) {
            #pragma unroll
            for (int k = 0; k < 9; k++) v[k] += t[k];
        }
    }
    int pk = __shfl_up_sync(0xffffffffu, key, 1);
    if (lane == 0 || pk != key) {
        float* p = dstBase + (size_t)key * PS;
        red_add4(p,     v[0], v[1], v[2], v[3]);
        red_add4(p + 4, v[4], v[5], v[6], v[7]);
        red_add1(p + 8, v[8]);
    }
}

// inline BN param computation: threads c<C write sP[c]=scale, sP[C+c]=shift.
__device__ __forceinline__ void compute_bn(const double* st, int C, double inv,
                                           const float* gamma, const float* beta,
                                           float* sP) {
    int c = threadIdx.x;
    if (c < C) {
        double mean = st[c] * inv;
        double var  = st[18 + c] * inv - mean * mean;
        float sc = __ldg(gamma + c) * rsqrtf((float)var + 1e-5f);
        sP[c] = sc;
        sP[C + c] = __ldg(beta + c) - (float)mean * sc;
    }
}

// flush register stats (C channels of s,q) to global double slot via smem racc[36]
__device__ __forceinline__ void stats_flush(const float* s, const float* q, int C,
                                            double* st, float* racc) {
    int lane = threadIdx.x & 31;
    for (int c = 0; c < C; c++) {
        float ss = warp_sum(s[c]);
        float qq = warp_sum(q[c]);
        if (lane == 0) { atomicAdd(&racc[c], ss); atomicAdd(&racc[18 + c], qq); }
    }
    __syncthreads();
    int t = threadIdx.x;
    if (t < C) atomicAdd(&st[t], (double)racc[t]);
    if (t >= 18 && t < 18 + C) atomicAdd(&st[t], (double)racc[t]);
}

// ---------------- kernels ----------------
__global__ void __launch_bounds__(256) k_init() {
    int i = blockIdx.x * 256 + threadIdx.x;
    if (i < GG * PS) { g_vn[i] = 0.f; g_gs[i] = 0.f; }
    if (i < 108) { g_stZ1[i] = 0.0; g_stZ2[i] = 0.0; }
    if (i < 72)  { g_stV1[i] = 0.0; g_stV2[i] = 0.0; }
    if (i < 9)   g_outacc[i] = 0.0;
}

// pack edge attrs: code = a0 + 6*a1 + 36*a2  (< 216), 1 byte per edge (run once)
__global__ void __launch_bounds__(256) k_pack(const int* __restrict__ ea) {
    int e = blockIdx.x * 256 + threadIdx.x;
    int a0 = __ldg(ea + (size_t)3 * e);
    int a1 = __ldg(ea + (size_t)3 * e + 1);
    int a2 = __ldg(ea + (size_t)3 * e + 2);
    g_eb[e] = (unsigned char)(a0 + 6 * a1 + 36 * a2);
}

// build combined bond tables for ALL 3 layers (one launch, 3 blocks)
__global__ void k_btab3(const float* __restrict__ bond_all) {
    const float* bond = bond_all + blockIdx.x * 162;
    float* bt = g_bt + blockIdx.x * (216 * 12);
    for (int i = threadIdx.x; i < 216 * 12; i += 256) {
        int code = i / 12, k = i % 12;
        float v = 0.f;
        if (k < 9) {
            int a0 = code % 6, a1 = (code / 6) % 6, a2 = code / 36;
            v = __ldg(bond + a0 * 9 + k) + __ldg(bond + 54 + a1 * 9 + k)
              + __ldg(bond + 108 + a2 * 9 + k);
        }
        bt[i] = v;
    }
}

// AtomEncoder: h_in = sum_f atom_emb[f, x[n,f]]; fp16 shadow; zero aggr buf; graph sums
__global__ void __launch_bounds__(256) k_atom(const float* __restrict__ atom_emb,
                                              const int* __restrict__ x,
                                              const int* __restrict__ batch) {
    int n = blockIdx.x * 256 + threadIdx.x;
    float h[9];
    #pragma unroll
    for (int k = 0; k < 9; k++) h[k] = 0.f;
    #pragma unroll
    for (int f = 0; f < 9; f++) {
        int v = __ldg(x + (size_t)n * 9 + f);
        const float* row = atom_emb + ((size_t)f * 119 + v) * 9;
        #pragma unroll
        for (int k = 0; k < 9; k++) h[k] += __ldg(row + k);
    }
    float4* hp = (float4*)(g_hin + (size_t)n * PS);
    hp[0] = make_float4(h[0], h[1], h[2], h[3]);
    hp[1] = make_float4(h[4], h[5], h[6], h[7]);
    hp[2] = make_float4(h[8], 0.f, 0.f, 0.f);
    store_h16(g_h16, n, h);
    zero_h16(g_ab, n);
    int g = __ldg(batch + n);
    seg_atomic9(g, h, g_gs);
}

// GIN message: relu(h16[src] + g_bt[l][code]) -> fp16 atomics into g_ab[dst].
// 1-sector gather + 1-sector scatter (2 red ops) per edge.
__global__ void __launch_bounds__(256) k_edge(const int* __restrict__ src,
                                              const int* __restrict__ dst, int l) {
    const float* bt = g_bt + l * (216 * 12);
    int e = blockIdx.x * 256 + threadIdx.x;
    int s = __ldg(src + e);
    int d = __ldg(dst + e);
    int code = (int)g_eb[e];
    const uint4* hp = (const uint4*)(g_h16 + (size_t)s * HS);
    uint4 u0 = __ldg(hp);                                   // halves 0..7
    unsigned int u8 = __ldg((const unsigned int*)(hp + 1)); // halves 8,9
    float2 f0 = __half22float2(*(__half2*)&u0.x);
    float2 f1 = __half22float2(*(__half2*)&u0.y);
    float2 f2 = __half22float2(*(__half2*)&u0.z);
    float2 f3 = __half22float2(*(__half2*)&u0.w);
    float2 f4 = __half22float2(*(__half2*)&u8);
    const float4* tp = (const float4*)(bt + code * 12);
    float4 t0 = __ldg(tp), t1 = __ldg(tp + 1), t2 = __ldg(tp + 2);
    float m0 = fmaxf(f0.x + t0.x, 0.f), m1 = fmaxf(f0.y + t0.y, 0.f);
    float m2 = fmaxf(f1.x + t0.z, 0.f), m3 = fmaxf(f1.y + t0.w, 0.f);
    float m4 = fmaxf(f2.x + t1.x, 0.f), m5 = fmaxf(f2.y + t1.y, 0.f);
    float m6 = fmaxf(f3.x + t1.z, 0.f), m7 = fmaxf(f3.y + t1.w, 0.f);
    float m8 = fmaxf(f4.x + t2.x, 0.f);
    __half2 p0 = __floats2half2_rn(m0, m1);
    __half2 p1 = __floats2half2_rn(m2, m3);
    __half2 p2 = __floats2half2_rn(m4, m5);
    __half2 p3 = __floats2half2_rn(m6, m7);
    __half2 p4 = __floats2half2_rn(m8, 0.f);
    __half* ab = g_ab + (size_t)d * HS;
    red_add_h2v4(ab, *(unsigned*)&p0, *(unsigned*)&p1, *(unsigned*)&p2, *(unsigned*)&p3);
    red_add_h2(ab + 8, *(unsigned*)&p4);
}

// z = (1+eps)*h_in + aggr(fp16) ; write z ; register stats of z@W1+b1 (18 ch)
// R6-proven form: NZI=8 fully unrolled, no reg cap
__global__ void __launch_bounds__(256) k_nodeZ(const float* __restrict__ W1,
                                               const float* __restrict__ b1,
                                               const float* __restrict__ eps_ptr, int l) {
    __shared__ float sW[162], sb[18], racc[36];
    int t = threadIdx.x;
    if (t < 162) sW[t] = W1[t];
    if (t < 18)  sb[t] = b1[t];
    if (t < 36)  racc[t] = 0.f;
    __syncthreads();
    float eps1 = 1.f + __ldg(eps_ptr);
    float s[18], q[18];
    #pragma unroll
    for (int c = 0; c < 18; c++) { s[c] = 0.f; q[c] = 0.f; }
    int base = blockIdx.x * (256 * NZI) + t;
    #pragma unroll
    for (int i = 0; i < NZI; i++) {
        int n = base + i * 256;
        const uint4* ap = (const uint4*)(g_ab + (size_t)n * HS);
        uint4 u0 = ap[0];
        unsigned int u8 = *(const unsigned int*)(ap + 1);
        float2 a0 = __half22float2(*(__half2*)&u0.x);
        float2 a1 = __half22float2(*(__half2*)&u0.y);
        float2 a2 = __half22float2(*(__half2*)&u0.z);
        float2 a3 = __half22float2(*(__half2*)&u0.w);
        float2 a4 = __half22float2(*(__half2*)&u8);
        const float4* hp = (const float4*)(g_hin + (size_t)n * PS);
        float4 ha = hp[0], hb = hp[1], hc = hp[2];
        float z[9];
        z[0] = fmaf(eps1, ha.x, a0.x);  z[1] = fmaf(eps1, ha.y, a0.y);
        z[2] = fmaf(eps1, ha.z, a1.x);  z[3] = fmaf(eps1, ha.w, a1.y);
        z[4] = fmaf(eps1, hb.x, a2.x);  z[5] = fmaf(eps1, hb.y, a2.y);
        z[6] = fmaf(eps1, hb.z, a3.x);  z[7] = fmaf(eps1, hb.w, a3.y);
        z[8] = fmaf(eps1, hc.x, a4.x);
        float4* bp = (float4*)(g_buf + (size_t)n * PS);
        bp[0] = make_float4(z[0], z[1], z[2], z[3]);
        bp[1] = make_float4(z[4], z[5], z[6], z[7]);
        bp[2] = make_float4(z[8], 0.f, 0.f, 0.f);
        #pragma unroll
        for (int c = 0; c < 18; c++) {
            float z1 = sb[c];
            #pragma unroll
            for (int j = 0; j < 9; j++) z1 = fmaf(z[j], sW[j * 18 + c], z1);
            s[c] += z1;
            q[c] = fmaf(z1, z1, q[c]);
        }
    }
    stats_flush(s, q, 18, g_stZ1 + l * 36, racc);
}

// y = relu(BN1(z@W1+b1)) (inline params); z2 = y@W2+b2; write z2; per-node stats of z2
__global__ void __launch_bounds__(256) k_nodeY(const float* __restrict__ W1,
                                               const float* __restrict__ b1,
                                               const float* __restrict__ W2,
                                               const float* __restrict__ b2,
                                               const float* __restrict__ bn1_g,
                                               const float* __restrict__ bn1_b, int l) {
    __shared__ float sW1[162], sW2[162], sb1[18], sb2[9], sP[36], racc[36];
    int t = threadIdx.x;
    if (t < 162) { sW1[t] = W1[t]; sW2[t] = W2[t]; }
    if (t < 18) sb1[t] = b1[t];
    if (t < 9)  sb2[t] = b2[t];
    if (t < 36) racc[t] = 0.f;
    compute_bn(g_stZ1 + l * 36, 18, 1.0 / (double)NN, bn1_g, bn1_b, sP);
    __syncthreads();
    int n = blockIdx.x * 256 + t;
    float4* bp = (float4*)(g_buf + (size_t)n * PS);
    float4 a = bp[0], b4 = bp[1], c4 = bp[2];
    float z[9] = {a.x, a.y, a.z, a.w, b4.x, b4.y, b4.z, b4.w, c4.x};
    float z2[9];
    #pragma unroll
    for (int c = 0; c < 9; c++) z2[c] = sb2[c];
    #pragma unroll
    for (int c = 0; c < 18; c++) {
        float z1 = sb1[c];
        #pragma unroll
        for (int j = 0; j < 9; j++) z1 = fmaf(z[j], sW1[j * 18 + c], z1);
        float y = fmaxf(fmaf(z1, sP[c], sP[18 + c]), 0.f);
        #pragma unroll
        for (int j = 0; j < 9; j++) z2[j] = fmaf(y, sW2[c * 9 + j], z2[j]);
    }
    bp[0] = make_float4(z2[0], z2[1], z2[2], z2[3]);
    bp[1] = make_float4(z2[4], z2[5], z2[6], z2[7]);
    bp[2] = make_float4(z2[8], 0.f, 0.f, 0.f);
    int lane = t & 31;
    #pragma unroll
    for (int c = 0; c < 9; c++) {
        float ss = warp_sum(z2[c]);
        float qq = warp_sum(z2[c] * z2[c]);
        if (lane == 0) { atomicAdd(&racc[c], ss); atomicAdd(&racc[18 + c], qq); }
    }
    __syncthreads();
    double* st = g_stZ2 + l * 36;
    if (t < 9) atomicAdd(&st[t], (double)racc[t]);
    if (t >= 18 && t < 27) atomicAdd(&st[t], (double)racc[t]);
}

// VN step A
__global__ void __launch_bounds__(256) k_vnA(const float* __restrict__ W1,
                                             const float* __restrict__ b1, int l) {
    __shared__ float sW[162], sb[18], racc[36];
    int t = threadIdx.x;
    if (t < 162) sW[t] = W1[t];
    if (t < 18)  sb[t] = b1[t];
    if (t < 36)  racc[t] = 0.f;
    __syncthreads();
    int g = blockIdx.x * 256 + t;
    float4* gp = (float4*)(g_gs + (size_t)g * PS);
    const float4* vp = (const float4*)(g_vn + (size_t)g * PS);
    float4 a = gp[0], b4 = gp[1], c4 = gp[2];
    float4 va = vp[0], vb = vp[1], vc = vp[2];
    float vt[9] = {a.x + va.x, a.y + va.y, a.z + va.z, a.w + va.w,
                   b4.x + vb.x, b4.y + vb.y, b4.z + vb.z, b4.w + vb.w, c4.x + vc.x};
    gp[0] = make_float4(vt[0], vt[1], vt[2], vt[3]);
    gp[1] = make_float4(vt[4], vt[5], vt[6], vt[7]);
    gp[2] = make_float4(vt[8], 0.f, 0.f, 0.f);
    float s[18], q[18];
    #pragma unroll
    for (int c = 0; c < 18; c++) {
        float u = sb[c];
        #pragma unroll
        for (int j = 0; j < 9; j++) u = fmaf(vt[j], sW[j * 18 + c], u);
        s[c] = u; q[c] = u * u;
    }
    stats_flush(s, q, 18, g_stV1 + l * 36, racc);
}

// VN step B
__global__ void __launch_bounds__(256) k_vnB(const float* __restrict__ W1,
                                             const float* __restrict__ b1,
                                             const float* __restrict__ W2,
                                             const float* __restrict__ b2,
                                             const float* __restrict__ bn_g,
                                             const float* __restrict__ bn_b, int l) {
    __shared__ float sW1[162], sW2[162], sb1[18], sb2[9], sP[36], racc[36];
    int t = threadIdx.x;
    if (t < 162) { sW1[t] = W1[t]; sW2[t] = W2[t]; }
    if (t < 18) sb1[t] = b1[t];
    if (t < 9)  sb2[t] = b2[t];
    if (t < 36) racc[t] = 0.f;
    compute_bn(g_stV1 + l * 36, 18, 1.0 / (double)GG, bn_g, bn_b, sP);
    __syncthreads();
    int g = blockIdx.x * 256 + t;
    float4* gp = (float4*)(g_gs + (size_t)g * PS);
    float4 a = gp[0], b4 = gp[1], c4 = gp[2];
    float vt[9] = {a.x, a.y, a.z, a.w, b4.x, b4.y, b4.z, b4.w, c4.x};
    float u2[9];
    #pragma unroll
    for (int c = 0; c < 9; c++) u2[c] = sb2[c];
    #pragma unroll
    for (int c = 0; c < 18; c++) {
        float u = sb1[c];
        #pragma unroll
        for (int j = 0; j < 9; j++) u = fmaf(vt[j], sW1[j * 18 + c], u);
        float y = fmaxf(fmaf(u, sP[c], sP[18 + c]), 0.f);
        #pragma unroll
        for (int j = 0; j < 9; j++) u2[j] = fmaf(y, sW2[c * 9 + j], u2[j]);
    }
    gp[0] = make_float4(u2[0], u2[1], u2[2], u2[3]);
    gp[1] = make_float4(u2[4], u2[5], u2[6], u2[7]);
    gp[2] = make_float4(u2[8], 0.f, 0.f, 0.f);
    float s[9], q[9];
    #pragma unroll
    for (int c = 0; c < 9; c++) { s[c] = u2[c]; q[c] = u2[c] * u2[c]; }
    stats_flush(s, q, 9, g_stV2 + l * 36, racc);
}

// VN step C
__global__ void __launch_bounds__(256) k_vnC(const float* __restrict__ bn_g,
                                             const float* __restrict__ bn_b, int l) {
    __shared__ float sP[18];
    compute_bn(g_stV2 + l * 36, 9, 1.0 / (double)GG, bn_g, bn_b, sP);
    __syncthreads();
    int g = blockIdx.x * 256 + threadIdx.x;
    float4* gp = (float4*)(g_gs + (size_t)g * PS);
    float4* vp = (float4*)(g_vn + (size_t)g * PS);
    float4 a = gp[0], b4 = gp[1], c4 = gp[2];
    float u2[9] = {a.x, a.y, a.z, a.w, b4.x, b4.y, b4.z, b4.w, c4.x};
    float4 va = vp[0], vb = vp[1], vc = vp[2];
    float vo[9] = {va.x, va.y, va.z, va.w, vb.x, vb.y, vb.z, vb.w, vc.x};
    #pragma unroll
    for (int k = 0; k < 9; k++)
        vo[k] += fmaxf(fmaf(u2[k], sP[k], sP[9 + k]), 0.f);
    vp[0] = make_float4(vo[0], vo[1], vo[2], vo[3]);
    vp[1] = make_float4(vo[4], vo[5], vo[6], vo[7]);
    vp[2] = make_float4(vo[8], 0.f, 0.f, 0.f);
    float4 zz = make_float4(0.f, 0.f, 0.f, 0.f);
    gp[0] = zz; gp[1] = zz; gp[2] = zz;
}

// layer finish (l<2): h_new = relu(BNout(z2)) + h_in; h_in' = h_new + vn'[batch];
// fp16 shadow refresh; zero aggr buffer for next layer
__global__ void __launch_bounds__(256) k_final_mid(const int* __restrict__ batch,
                                                   const float* __restrict__ bn_g,
                                                   const float* __restrict__ bn_b,
                                                   int l, int accumGS) {
    __shared__ float sP[18];
    compute_bn(g_stZ2 + l * 36, 9, 1.0 / (double)NN, bn_g, bn_b, sP);
    __syncthreads();
    int n = blockIdx.x * 256 + threadIdx.x;
    float4* bp = (float4*)(g_buf + (size_t)n * PS);
    float4* hp = (float4*)(g_hin + (size_t)n * PS);
    float4 a = bp[0], b4 = bp[1], c4 = bp[2];
    float z2[9] = {a.x, a.y, a.z, a.w, b4.x, b4.y, b4.z, b4.w, c4.x};
    float4 ha = hp[0], hb = hp[1], hc = hp[2];
    float hi[9] = {ha.x, ha.y, ha.z, ha.w, hb.x, hb.y, hb.z, hb.w, hc.x};
    int g = __ldg(batch + n);
    const float4* vp = (const float4*)(g_vn + (size_t)g * PS);
    float4 va = vp[0], vb = vp[1], vc = vp[2];
    float vn9[9] = {va.x, va.y, va.z, va.w, vb.x, vb.y, vb.z, vb.w, vc.x};
    float hx[9];
    #pragma unroll
    for (int k = 0; k < 9; k++) {
        float zn = fmaxf(fmaf(z2[k], sP[k], sP[9 + k]), 0.f);
        hx[k] = zn + hi[k] + vn9[k];
    }
    hp[0] = make_float4(hx[0], hx[1], hx[2], hx[3]);
    hp[1] = make_float4(hx[4], hx[5], hx[6], hx[7]);
    hp[2] = make_float4(hx[8], 0.f, 0.f, 0.f);
    store_h16(g_h16, n, hx);
    zero_h16(g_ab, n);
    if (accumGS) seg_atomic9(g, hx, g_gs);
}

// last layer finish: h = BNout(z2) + h_in (no relu); global sum
__global__ void __launch_bounds__(256) k_final_last(const float* __restrict__ bn_g,
                                                    const float* __restrict__ bn_b, int l) {
    __shared__ float sP[18], racc[9];
    compute_bn(g_stZ2 + l * 36, 9, 1.0 / (double)NN, bn_g, bn_b, sP);
    if (threadIdx.x < 9) racc[threadIdx.x] = 0.f;
    __syncthreads();
    int n = blockIdx.x * 256 + threadIdx.x;
    const float4* bp = (const float4*)(g_buf + (size_t)n * PS);
    const float4* hp = (const float4*)(g_hin + (size_t)n * PS);
    float4 a = bp[0], b4 = bp[1], c4 = bp[2];
    float z2[9] = {a.x, a.y, a.z, a.w, b4.x, b4.y, b4.z, b4.w, c4.x};
    float4 ha = hp[0], hb = hp[1], hc = hp[2];
    float hi[9] = {ha.x, ha.y, ha.z, ha.w, hb.x, hb.y, hb.z, hb.w, hc.x};
    int lane = threadIdx.x & 31;
    #pragma unroll
    for (int k = 0; k < 9; k++) {
        float h = fmaf(z2[k], sP[k], sP[9 + k]) + hi[k];
        float v = warp_sum(h);
        if (lane == 0) atomicAdd(&racc[k], v);
    }
    __syncthreads();
    if (threadIdx.x < 9) atomicAdd(&g_outacc[threadIdx.x], (double)racc[threadIdx.x]);
}

__global__ void k_out(float* __restrict__ out) {
    if (threadIdx.x < 9) out[threadIdx.x] = (float)g_outacc[threadIdx.x];
}

// ---------------- host ----------------
extern "C" void kernel_launch(void* const* d_in, const int* in_sizes, int n_in,
                              void* d_out, int out_size) {
    const float* atom_emb = (const float*)d_in[0];
    const float* bond_emb = (const float*)d_in[1];
    const float* eps_gin  = (const float*)d_in[2];
    const float* W1       = (const float*)d_in[3];
    const float* b1       = (const float*)d_in[4];
    const float* bn1_g    = (const float*)d_in[5];
    const float* bn1_b    = (const float*)d_in[6];
    const float* W2       = (const float*)d_in[7];
    const float* b2       = (const float*)d_in[8];
    const float* bno_g    = (const float*)d_in[9];
    const float* bno_b    = (const float*)d_in[10];
    const float* vnW1     = (const float*)d_in[11];
    const float* vnb1     = (const float*)d_in[12];
    const float* vnbn1_g  = (const float*)d_in[13];
    const float* vnbn1_b  = (const float*)d_in[14];
    const float* vnW2     = (const float*)d_in[15];
    const float* vnb2     = (const float*)d_in[16];
    const float* vnbn2_g  = (const float*)d_in[17];
    const float* vnbn2_b  = (const float*)d_in[18];
    const int*   x        = (const int*)d_in[19];
    const int*   eidx     = (const int*)d_in[20];
    const int*   eattr    = (const int*)d_in[21];
    const int*   batch    = (const int*)d_in[22];
    (void)in_sizes; (void)n_in; (void)out_size;

    k_init<<<(GG * PS + 255) / 256, 256>>>();
    k_pack<<<NB_E, 256>>>(eattr);
    k_btab3<<<3, 256>>>(bond_emb);
    k_atom<<<NB_N, 256>>>(atom_emb, x, batch);

    for (int l = 0; l < 3; l++) {
        k_edge<<<NB_E, 256>>>(eidx, eidx + EE, l);
        k_nodeZ<<<NB_Z, 256>>>(W1 + l * 162, b1 + l * 18, eps_gin + l, l);
        k_nodeY<<<NB_N, 256>>>(W1 + l * 162, b1 + l * 18, W2 + l * 162, b2 + l * 9,
                               bn1_g + l * 18, bn1_b + l * 18, l);
        if (l < 2) {
            k_vnA<<<NB_G, 256>>>(vnW1 + l * 162, vnb1 + l * 18, l);
            k_vnB<<<NB_G, 256>>>(vnW1 + l * 162, vnb1 + l * 18, vnW2 + l * 162,
                                 vnb2 + l * 9, vnbn1_g + l * 18, vnbn1_b + l * 18, l);
            k_vnC<<<NB_G, 256>>>(vnbn2_g + l * 9, vnbn2_b + l * 9, l);
            k_final_mid<<<NB_N, 256>>>(batch, bno_g + l * 9, bno_b + l * 9, l,
                                       (l == 0) ? 1 : 0);
        } else {
            k_final_last<<<NB_N, 256>>>(bno_g + l * 9, bno_b + l * 9, l);
        }
    }
    k_out<<<1, 32>>>((float*)d_out);
}

// round 14
// speedup vs baseline: 2.7222x; 1.0173x over previous
#include <cuda_runtime.h>
#include <cuda_fp16.h>

#define NN 1048576
#define EE 8388608
#define GG 32768
#define PS 12   // fp32 row stride (9 ch + 3 pad) -> 48B
#define HS 16   // fp16 row stride in halves -> 32B (1 sector)
#define NZI 8                           // nodes/thread in k_nodeZ (R6-proven full unroll)
#define NB_Z (NN / (256 * NZI))         // 512
#define NB_N (NN / 256)                 // 4096
#define NB_E (EE / 256)                 // 32768
#define NB_G (GG / 256)                 // 128

// ---------------- device state (no allocation allowed) ----------------
__device__ __align__(16) float  g_hin[(size_t)NN * PS];   // fp32 h_in (residual path)
__device__ __align__(32) __half g_h16[(size_t)NN * HS];   // fp16 shadow of h_in (32MB)
__device__ __align__(32) __half g_ab [(size_t)NN * HS];   // fp16 edge-aggr accumulator (32MB)
__device__ __align__(32) __half g_zb [(size_t)NN * HS];   // fp16 z / z2 inter-kernel buffer (32MB)
__device__ __align__(16) float  g_vn [(size_t)GG * PS];
__device__ __align__(16) float  g_gs [(size_t)GG * PS];
__device__ unsigned char g_eb[(size_t)EE];           // packed edge attr codes (<216)
__device__ __align__(16) float g_bt[3 * 216 * 12];   // combined bond tables, all layers
// per-layer raw BN stats: sum at [c], sumsq at [18+c], 36-stride per layer
__device__ double g_stZ1[3 * 36];
__device__ double g_stZ2[3 * 36];
__device__ double g_stV1[2 * 36];
__device__ double g_stV2[2 * 36];
__device__ double g_outacc[9];

// ---------------- helpers ----------------
__device__ __forceinline__ void red_add4(float* p, float a, float b, float c, float d) {
    asm volatile("red.global.add.v4.f32 [%0], {%1,%2,%3,%4};"
                 :: "l"(__cvta_generic_to_global(p)), "f"(a), "f"(b), "f"(c), "f"(d) : "memory");
}
__device__ __forceinline__ void red_add1(float* p, float a) {
    asm volatile("red.global.add.f32 [%0], %1;"
                 :: "l"(__cvta_generic_to_global(p)), "f"(a) : "memory");
}
// fp16x2 vector reductions (sm_90+)
__device__ __forceinline__ void red_add_h2v4(__half* p, unsigned a, unsigned b,
                                             unsigned c, unsigned d) {
    asm volatile("red.global.add.noftz.v4.f16x2 [%0], {%1,%2,%3,%4};"
                 :: "l"(__cvta_generic_to_global(p)), "r"(a), "r"(b), "r"(c), "r"(d) : "memory");
}
__device__ __forceinline__ void red_add_h2(__half* p, unsigned a) {
    asm volatile("red.global.add.noftz.f16x2 [%0], %1;"
                 :: "l"(__cvta_generic_to_global(p)), "r"(a) : "memory");
}
__device__ __forceinline__ float warp_sum(float v) {
    #pragma unroll
    for (int off = 16; off > 0; off >>= 1) v += __shfl_down_sync(0xffffffffu, v, off);
    return v;
}

// store 9 floats as a 32B fp16 row AND return the rounded values (for consistent stats)
__device__ __forceinline__ void store_h16_rounded(__half* basePtr, int n,
                                                  const float* h, float* hr) {
    __half2 hh[8];
    hh[0] = __floats2half2_rn(h[0], h[1]);
    hh[1] = __floats2half2_rn(h[2], h[3]);
    hh[2] = __floats2half2_rn(h[4], h[5]);
    hh[3] = __floats2half2_rn(h[6], h[7]);
    hh[4] = __floats2half2_rn(h[8], 0.f);
    hh[5] = hh[6] = hh[7] = __floats2half2_rn(0.f, 0.f);
    uint4* sp = (uint4*)(basePtr + (size_t)n * HS);
    sp[0] = *(uint4*)&hh[0];
    sp[1] = *(uint4*)&hh[4];
    if (hr) {
        float2 r0 = __half22float2(hh[0]), r1 = __half22float2(hh[1]);
        float2 r2 = __half22float2(hh[2]), r3 = __half22float2(hh[3]);
        float2 r4 = __half22float2(hh[4]);
        hr[0] = r0.x; hr[1] = r0.y; hr[2] = r1.x; hr[3] = r1.y;
        hr[4] = r2.x; hr[5] = r2.y; hr[6] = r3.x; hr[7] = r3.y; hr[8] = r4.x;
    }
}
__device__ __forceinline__ void store_h16(__half* basePtr, int n, const float* h) {
    store_h16_rounded(basePtr, n, h, (float*)0);
}
__device__ __forceinline__ void load_h16(const __half* basePtr, int n, float* out) {
    const uint4* ap = (const uint4*)(basePtr + (size_t)n * HS);
    uint4 u0 = ap[0];
    unsigned int u8 = *(const unsigned int*)(ap + 1);
    float2 a0 = __half22float2(*(__half2*)&u0.x);
    float2 a1 = __half22float2(*(__half2*)&u0.y);
    float2 a2 = __half22float2(*(__half2*)&u0.z);
    float2 a3 = __half22float2(*(__half2*)&u0.w);
    float2 a4 = __half22float2(*(__half2*)&u8);
    out[0] = a0.x; out[1] = a0.y; out[2] = a1.x; out[3] = a1.y;
    out[4] = a2.x; out[5] = a2.y; out[6] = a3.x; out[7] = a3.y; out[8] = a4.x;
}
__device__ __forceinline__ void zero_h16(__half* basePtr, int n) {
    uint4 z = make_uint4(0u, 0u, 0u, 0u);
    uint4* sp = (uint4*)(basePtr + (size_t)n * HS);
    sp[0] = z; sp[1] = z;
}

// warp-level segmented sum over sorted keys, then 3 vector atomics per segment head
__device__ __forceinline__ void seg_atomic9(int key, float v[9], float* dstBase) {
    int lane = threadIdx.x & 31;
    #pragma unroll
    for (int off = 1; off < 32; off <<= 1) {
        int nk = __shfl_down_sync(0xffffffffu, key, off);
        float t[9];
        #pragma unroll
        for (int k = 0; k < 9; k++) t[k] = __shfl_down_sync(0xffffffffu, v[k], off);
        if (lane + off < 32 && nk == key) {
            #pragma unroll
            for (int k = 0; k < 9; k++) v[k] += t[k];
        }
    }
    int pk = __shfl_up_sync(0xffffffffu, key, 1);
    if (lane == 0 || pk != key) {
        float* p = dstBase + (size_t)key * PS;
        red_add4(p,     v[0], v[1], v[2], v[3]);
        red_add4(p + 4, v[4], v[5], v[6], v[7]);
        red_add1(p + 8, v[8]);
    }
}

// inline BN param computation: threads c<C write sP[c]=scale, sP[C+c]=shift.
__device__ __forceinline__ void compute_bn(const double* st, int C, double inv,
                                           const float* gamma, const float* beta,
                                           float* sP) {
    int c = threadIdx.x;
    if (c < C) {
        double mean = st[c] * inv;
        double var  = st[18 + c] * inv - mean * mean;
        float sc = __ldg(gamma + c) * rsqrtf((float)var + 1e-5f);
        sP[c] = sc;
        sP[C + c] = __ldg(beta + c) - (float)mean * sc;
    }
}

// flush register stats (C channels of s,q) to global double slot via smem racc[36]
__device__ __forceinline__ void stats_flush(const float* s, const float* q, int C,
                                            double* st, float* racc) {
    int lane = threadIdx.x & 31;
    for (int c = 0; c < C; c++) {
        float ss = warp_sum(s[c]);
        float qq = warp_sum(q[c]);
        if (lane == 0) { atomicAdd(&racc[c], ss); atomicAdd(&racc[18 + c], qq); }
    }
    __syncthreads();
    int t = threadIdx.x;
    if (t < C) atomicAdd(&st[t], (double)racc[t]);
    if (t >= 18 && t < 18 + C) atomicAdd(&st[t], (double)racc[t]);
}

// ---------------- kernels ----------------
__global__ void __launch_bounds__(256) k_init() {
    int i = blockIdx.x * 256 + threadIdx.x;
    if (i < GG * PS) { g_vn[i] = 0.f; g_gs[i] = 0.f; }
    if (i < 108) { g_stZ1[i] = 0.0; g_stZ2[i] = 0.0; }
    if (i < 72)  { g_stV1[i] = 0.0; g_stV2[i] = 0.0; }
    if (i < 9)   g_outacc[i] = 0.0;
}

// pack edge attrs: code = a0 + 6*a1 + 36*a2  (< 216), 1 byte per edge (run once)
__global__ void __launch_bounds__(256) k_pack(const int* __restrict__ ea) {
    int e = blockIdx.x * 256 + threadIdx.x;
    int a0 = __ldg(ea + (size_t)3 * e);
    int a1 = __ldg(ea + (size_t)3 * e + 1);
    int a2 = __ldg(ea + (size_t)3 * e + 2);
    g_eb[e] = (unsigned char)(a0 + 6 * a1 + 36 * a2);
}

// build combined bond tables for ALL 3 layers (one launch, 3 blocks)
__global__ void k_btab3(const float* __restrict__ bond_all) {
    const float* bond = bond_all + blockIdx.x * 162;
    float* bt = g_bt + blockIdx.x * (216 * 12);
    for (int i = threadIdx.x; i < 216 * 12; i += 256) {
        int code = i / 12, k = i % 12;
        float v = 0.f;
        if (k < 9) {
            int a0 = code % 6, a1 = (code / 6) % 6, a2 = code / 36;
            v = __ldg(bond + a0 * 9 + k) + __ldg(bond + 54 + a1 * 9 + k)
              + __ldg(bond + 108 + a2 * 9 + k);
        }
        bt[i] = v;
    }
}

// AtomEncoder: h_in = sum_f atom_emb[f, x[n,f]]; fp16 shadow; zero aggr buf; graph sums
__global__ void __launch_bounds__(256) k_atom(const float* __restrict__ atom_emb,
                                              const int* __restrict__ x,
                                              const int* __restrict__ batch) {
    int n = blockIdx.x * 256 + threadIdx.x;
    float h[9];
    #pragma unroll
    for (int k = 0; k < 9; k++) h[k] = 0.f;
    #pragma unroll
    for (int f = 0; f < 9; f++) {
        int v = __ldg(x + (size_t)n * 9 + f);
        const float* row = atom_emb + ((size_t)f * 119 + v) * 9;
        #pragma unroll
        for (int k = 0; k < 9; k++) h[k] += __ldg(row + k);
    }
    float4* hp = (float4*)(g_hin + (size_t)n * PS);
    hp[0] = make_float4(h[0], h[1], h[2], h[3]);
    hp[1] = make_float4(h[4], h[5], h[6], h[7]);
    hp[2] = make_float4(h[8], 0.f, 0.f, 0.f);
    store_h16(g_h16, n, h);
    zero_h16(g_ab, n);
    int g = __ldg(batch + n);
    seg_atomic9(g, h, g_gs);
}

// GIN message: relu(h16[src] + g_bt[l][code]) -> fp16 atomics into g_ab[dst].
// 1-sector gather + 1-sector scatter (2 red ops) per edge.
__global__ void __launch_bounds__(256) k_edge(const int* __restrict__ src,
                                              const int* __restrict__ dst, int l) {
    const float* bt = g_bt + l * (216 * 12);
    int e = blockIdx.x * 256 + threadIdx.x;
    int s = __ldg(src + e);
    int d = __ldg(dst + e);
    int code = (int)g_eb[e];
    const uint4* hp = (const uint4*)(g_h16 + (size_t)s * HS);
    uint4 u0 = __ldg(hp);                                   // halves 0..7
    unsigned int u8 = __ldg((const unsigned int*)(hp + 1)); // halves 8,9
    float2 f0 = __half22float2(*(__half2*)&u0.x);
    float2 f1 = __half22float2(*(__half2*)&u0.y);
    float2 f2 = __half22float2(*(__half2*)&u0.z);
    float2 f3 = __half22float2(*(__half2*)&u0.w);
    float2 f4 = __half22float2(*(__half2*)&u8);
    const float4* tp = (const float4*)(bt + code * 12);
    float4 t0 = __ldg(tp), t1 = __ldg(tp + 1), t2 = __ldg(tp + 2);
    float m0 = fmaxf(f0.x + t0.x, 0.f), m1 = fmaxf(f0.y + t0.y, 0.f);
    float m2 = fmaxf(f1.x + t0.z, 0.f), m3 = fmaxf(f1.y + t0.w, 0.f);
    float m4 = fmaxf(f2.x + t1.x, 0.f), m5 = fmaxf(f2.y + t1.y, 0.f);
    float m6 = fmaxf(f3.x + t1.z, 0.f), m7 = fmaxf(f3.y + t1.w, 0.f);
    float m8 = fmaxf(f4.x + t2.x, 0.f);
    __half2 p0 = __floats2half2_rn(m0, m1);
    __half2 p1 = __floats2half2_rn(m2, m3);
    __half2 p2 = __floats2half2_rn(m4, m5);
    __half2 p3 = __floats2half2_rn(m6, m7);
    __half2 p4 = __floats2half2_rn(m8, 0.f);
    __half* ab = g_ab + (size_t)d * HS;
    red_add_h2v4(ab, *(unsigned*)&p0, *(unsigned*)&p1, *(unsigned*)&p2, *(unsigned*)&p3);
    red_add_h2(ab + 8, *(unsigned*)&p4);
}

// z = (1+eps)*h_in + aggr(fp16) ; write z (fp16, rounded) ; stats on ROUNDED z@W1+b1
// R6-proven form: NZI=8 fully unrolled, no reg cap
__global__ void __launch_bounds__(256) k_nodeZ(const float* __restrict__ W1,
                                               const float* __restrict__ b1,
                                               const float* __restrict__ eps_ptr, int l) {
    __shared__ float sW[162], sb[18], racc[36];
    int t = threadIdx.x;
    if (t < 162) sW[t] = W1[t];
    if (t < 18)  sb[t] = b1[t];
    if (t < 36)  racc[t] = 0.f;
    __syncthreads();
    float eps1 = 1.f + __ldg(eps_ptr);
    float s[18], q[18];
    #pragma unroll
    for (int c = 0; c < 18; c++) { s[c] = 0.f; q[c] = 0.f; }
    int base = blockIdx.x * (256 * NZI) + t;
    #pragma unroll
    for (int i = 0; i < NZI; i++) {
        int n = base + i * 256;
        float a9[9];
        load_h16(g_ab, n, a9);
        const float4* hp = (const float4*)(g_hin + (size_t)n * PS);
        float4 ha = hp[0], hb = hp[1], hc = hp[2];
        float z[9];
        z[0] = fmaf(eps1, ha.x, a9[0]); z[1] = fmaf(eps1, ha.y, a9[1]);
        z[2] = fmaf(eps1, ha.z, a9[2]); z[3] = fmaf(eps1, ha.w, a9[3]);
        z[4] = fmaf(eps1, hb.x, a9[4]); z[5] = fmaf(eps1, hb.y, a9[5]);
        z[6] = fmaf(eps1, hb.z, a9[6]); z[7] = fmaf(eps1, hb.w, a9[7]);
        z[8] = fmaf(eps1, hc.x, a9[8]);
        float zr[9];
        store_h16_rounded(g_zb, n, z, zr);   // rounded values = what nodeY will read
        #pragma unroll
        for (int c = 0; c < 18; c++) {
            float z1 = sb[c];
            #pragma unroll
            for (int j = 0; j < 9; j++) z1 = fmaf(zr[j], sW[j * 18 + c], z1);
            s[c] += z1;
            q[c] = fmaf(z1, z1, q[c]);
        }
    }
    stats_flush(s, q, 18, g_stZ1 + l * 36, racc);
}

// y = relu(BN1(z@W1+b1)) (inline params); z2 = y@W2+b2; write z2 (fp16, rounded);
// stats on ROUNDED z2 (what final reads)
__global__ void __launch_bounds__(256) k_nodeY(const float* __restrict__ W1,
                                               const float* __restrict__ b1,
                                               const float* __restrict__ W2,
                                               const float* __restrict__ b2,
                                               const float* __restrict__ bn1_g,
                                               const float* __restrict__ bn1_b, int l) {
    __shared__ float sW1[162], sW2[162], sb1[18], sb2[9], sP[36], racc[36];
    int t = threadIdx.x;
    if (t < 162) { sW1[t] = W1[t]; sW2[t] = W2[t]; }
    if (t < 18) sb1[t] = b1[t];
    if (t < 9)  sb2[t] = b2[t];
    if (t < 36) racc[t] = 0.f;
    compute_bn(g_stZ1 + l * 36, 18, 1.0 / (double)NN, bn1_g, bn1_b, sP);
    __syncthreads();
    int n = blockIdx.x * 256 + t;
    float z[9];
    load_h16(g_zb, n, z);
    float z2[9];
    #pragma unroll
    for (int c = 0; c < 9; c++) z2[c] = sb2[c];
    #pragma unroll
    for (int c = 0; c < 18; c++) {
        float z1 = sb1[c];
        #pragma unroll
        for (int j = 0; j < 9; j++) z1 = fmaf(z[j], sW1[j * 18 + c], z1);
        float y = fmaxf(fmaf(z1, sP[c], sP[18 + c]), 0.f);
        #pragma unroll
        for (int j = 0; j < 9; j++) z2[j] = fmaf(y, sW2[c * 9 + j], z2[j]);
    }
    float z2r[9];
    store_h16_rounded(g_zb, n, z2, z2r);
    int lane = t & 31;
    #pragma unroll
    for (int c = 0; c < 9; c++) {
        float ss = warp_sum(z2r[c]);
        float qq = warp_sum(z2r[c] * z2r[c]);
        if (lane == 0) { atomicAdd(&racc[c], ss); atomicAdd(&racc[18 + c], qq); }
    }
    __syncthreads();
    double* st = g_stZ2 + l * 36;
    if (t < 9) atomicAdd(&st[t], (double)racc[t]);
    if (t >= 18 && t < 27) atomicAdd(&st[t], (double)racc[t]);
}

// VN step A
__global__ void __launch_bounds__(256) k_vnA(const float* __restrict__ W1,
                                             const float* __restrict__ b1, int l) {
    __shared__ float sW[162], sb[18], racc[36];
    int t = threadIdx.x;
    if (t < 162) sW[t] = W1[t];
    if (t < 18)  sb[t] = b1[t];
    if (t < 36)  racc[t] = 0.f;
    __syncthreads();
    int g = blockIdx.x * 256 + t;
    float4* gp = (float4*)(g_gs + (size_t)g * PS);
    const float4* vp = (const float4*)(g_vn + (size_t)g * PS);
    float4 a = gp[0], b4 = gp[1], c4 = gp[2];
    float4 va = vp[0], vb = vp[1], vc = vp[2];
    float vt[9] = {a.x + va.x, a.y + va.y, a.z + va.z, a.w + va.w,
                   b4.x + vb.x, b4.y + vb.y, b4.z + vb.z, b4.w + vb.w, c4.x + vc.x};
    gp[0] = make_float4(vt[0], vt[1], vt[2], vt[3]);
    gp[1] = make_float4(vt[4], vt[5], vt[6], vt[7]);
    gp[2] = make_float4(vt[8], 0.f, 0.f, 0.f);
    float s[18], q[18];
    #pragma unroll
    for (int c = 0; c < 18; c++) {
        float u = sb[c];
        #pragma unroll
        for (int j = 0; j < 9; j++) u = fmaf(vt[j], sW[j * 18 + c], u);
        s[c] = u; q[c] = u * u;
    }
    stats_flush(s, q, 18, g_stV1 + l * 36, racc);
}

// VN step B
__global__ void __launch_bounds__(256) k_vnB(const float* __restrict__ W1,
                                             const float* __restrict__ b1,
                                             const float* __restrict__ W2,
                                             const float* __restrict__ b2,
                                             const float* __restrict__ bn_g,
                                             const float* __restrict__ bn_b, int l) {
    __shared__ float sW1[162], sW2[162], sb1[18], sb2[9], sP[36], racc[36];
    int t = threadIdx.x;
    if (t < 162) { sW1[t] = W1[t]; sW2[t] = W2[t]; }
    if (t < 18) sb1[t] = b1[t];
    if (t < 9)  sb2[t] = b2[t];
    if (t < 36) racc[t] = 0.f;
    compute_bn(g_stV1 + l * 36, 18, 1.0 / (double)GG, bn_g, bn_b, sP);
    __syncthreads();
    int g = blockIdx.x * 256 + t;
    float4* gp = (float4*)(g_gs + (size_t)g * PS);
    float4 a = gp[0], b4 = gp[1], c4 = gp[2];
    float vt[9] = {a.x, a.y, a.z, a.w, b4.x, b4.y, b4.z, b4.w, c4.x};
    float u2[9];
    #pragma unroll
    for (int c = 0; c < 9; c++) u2[c] = sb2[c];
    #pragma unroll
    for (int c = 0; c < 18; c++) {
        float u = sb1[c];
        #pragma unroll
        for (int j = 0; j < 9; j++) u = fmaf(vt[j], sW1[j * 18 + c], u);
        float y = fmaxf(fmaf(u, sP[c], sP[18 + c]), 0.f);
        #pragma unroll
        for (int j = 0; j < 9; j++) u2[j] = fmaf(y, sW2[c * 9 + j], u2[j]);
    }
    gp[0] = make_float4(u2[0], u2[1], u2[2], u2[3]);
    gp[1] = make_float4(u2[4], u2[5], u2[6], u2[7]);
    gp[2] = make_float4(u2[8], 0.f, 0.f, 0.f);
    float s[9], q[9];
    #pragma unroll
    for (int c = 0; c < 9; c++) { s[c] = u2[c]; q[c] = u2[c] * u2[c]; }
    stats_flush(s, q, 9, g_stV2 + l * 36, racc);
}

// VN step C
__global__ void __launch_bounds__(256) k_vnC(const float* __restrict__ bn_g,
                                             const float* __restrict__ bn_b, int l) {
    __shared__ float sP[18];
    compute_bn(g_stV2 + l * 36, 9, 1.0 / (double)GG, bn_g, bn_b, sP);
    __syncthreads();
    int g = blockIdx.x * 256 + threadIdx.x;
    float4* gp = (float4*)(g_gs + (size_t)g * PS);
    float4* vp = (float4*)(g_vn + (size_t)g * PS);
    float4 a = gp[0], b4 = gp[1], c4 = gp[2];
    float u2[9] = {a.x, a.y, a.z, a.w, b4.x, b4.y, b4.z, b4.w, c4.x};
    float4 va = vp[0], vb = vp[1], vc = vp[2];
    float vo[9] = {va.x, va.y, va.z, va.w, vb.x, vb.y, vb.z, vb.w, vc.x};
    #pragma unroll
    for (int k = 0; k < 9; k++)
        vo[k] += fmaxf(fmaf(u2[k], sP[k], sP[9 + k]), 0.f);
    vp[0] = make_float4(vo[0], vo[1], vo[2], vo[3]);
    vp[1] = make_float4(vo[4], vo[5], vo[6], vo[7]);
    vp[2] = make_float4(vo[8], 0.f, 0.f, 0.f);
    float4 zz = make_float4(0.f, 0.f, 0.f, 0.f);
    gp[0] = zz; gp[1] = zz; gp[2] = zz;
}

// layer finish (l<2): h_new = relu(BNout(z2)) + h_in; h_in' = h_new + vn'[batch];
// fp16 shadow refresh; zero aggr buffer for next layer
__global__ void __launch_bounds__(256) k_final_mid(const int* __restrict__ batch,
                                                   const float* __restrict__ bn_g,
                                                   const float* __restrict__ bn_b,
                                                   int l, int accumGS) {
    __shared__ float sP[18];
    compute_bn(g_stZ2 + l * 36, 9, 1.0 / (double)NN, bn_g, bn_b, sP);
    __syncthreads();
    int n = blockIdx.x * 256 + threadIdx.x;
    float z2[9];
    load_h16(g_zb, n, z2);
    float4* hp = (float4*)(g_hin + (size_t)n * PS);
    float4 ha = hp[0], hb = hp[1], hc = hp[2];
    float hi[9] = {ha.x, ha.y, ha.z, ha.w, hb.x, hb.y, hb.z, hb.w, hc.x};
    int g = __ldg(batch + n);
    const float4* vp = (const float4*)(g_vn + (size_t)g * PS);
    float4 va = vp[0], vb = vp[1], vc = vp[2];
    float vn9[9] = {va.x, va.y, va.z, va.w, vb.x, vb.y, vb.z, vb.w, vc.x};
    float hx[9];
    #pragma unroll
    for (int k = 0; k < 9; k++) {
        float zn = fmaxf(fmaf(z2[k], sP[k], sP[9 + k]), 0.f);
        hx[k] = zn + hi[k] + vn9[k];
    }
    hp[0] = make_float4(hx[0], hx[1], hx[2], hx[3]);
    hp[1] = make_float4(hx[4], hx[5], hx[6], hx[7]);
    hp[2] = make_float4(hx[8], 0.f, 0.f, 0.f);
    store_h16(g_h16, n, hx);
    zero_h16(g_ab, n);
    if (accumGS) seg_atomic9(g, hx, g_gs);
}

// last layer finish: h = BNout(z2) + h_in (no relu); global sum
__global__ void __launch_bounds__(256) k_final_last(const float* __restrict__ bn_g,
                                                    const float* __restrict__ bn_b, int l) {
    __shared__ float sP[18], racc[9];
    compute_bn(g_stZ2 + l * 36, 9, 1.0 / (double)NN, bn_g, bn_b, sP);
    if (threadIdx.x < 9) racc[threadIdx.x] = 0.f;
    __syncthreads();
    int n = blockIdx.x * 256 + threadIdx.x;
    float z2[9];
    load_h16(g_zb, n, z2);
    const float4* hp = (const float4*)(g_hin + (size_t)n * PS);
    float4 ha = hp[0], hb = hp[1], hc = hp[2];
    float hi[9] = {ha.x, ha.y, ha.z, ha.w, hb.x, hb.y, hb.z, hb.w, hc.x};
    int lane = threadIdx.x & 31;
    #pragma unroll
    for (int k = 0; k < 9; k++) {
        float h = fmaf(z2[k], sP[k], sP[9 + k]) + hi[k];
        float v = warp_sum(h);
        if (lane == 0) atomicAdd(&racc[k], v);
    }
    __syncthreads();
    if (threadIdx.x < 9) atomicAdd(&g_outacc[threadIdx.x], (double)racc[threadIdx.x]);
}

__global__ void k_out(float* __restrict__ out) {
    if (threadIdx.x < 9) out[threadIdx.x] = (float)g_outacc[threadIdx.x];
}

// ---------------- host ----------------
extern "C" void kernel_launch(void* const* d_in, const int* in_sizes, int n_in,
                              void* d_out, int out_size) {
    const float* atom_emb = (const float*)d_in[0];
    const float* bond_emb = (const float*)d_in[1];
    const float* eps_gin  = (const float*)d_in[2];
    const float* W1       = (const float*)d_in[3];
    const float* b1       = (const float*)d_in[4];
    const float* bn1_g    = (const float*)d_in[5];
    const float* bn1_b    = (const float*)d_in[6];
    const float* W2       = (const float*)d_in[7];
    const float* b2       = (const float*)d_in[8];
    const float* bno_g    = (const float*)d_in[9];
    const float* bno_b    = (const float*)d_in[10];
    const float* vnW1     = (const float*)d_in[11];
    const float* vnb1     = (const float*)d_in[12];
    const float* vnbn1_g  = (const float*)d_in[13];
    const float* vnbn1_b  = (const float*)d_in[14];
    const float* vnW2     = (const float*)d_in[15];
    const float* vnb2     = (const float*)d_in[16];
    const float* vnbn2_g  = (const float*)d_in[17];
    const float* vnbn2_b  = (const float*)d_in[18];
    const int*   x        = (const int*)d_in[19];
    const int*   eidx     = (const int*)d_in[20];
    const int*   eattr    = (const int*)d_in[21];
    const int*   batch    = (const int*)d_in[22];
    (void)in_sizes; (void)n_in; (void)out_size;

    k_init<<<(GG * PS + 255) / 256, 256>>>();
    k_pack<<<NB_E, 256>>>(eattr);
    k_btab3<<<3, 256>>>(bond_emb);
    k_atom<<<NB_N, 256>>>(atom_emb, x, batch);

    for (int l = 0; l < 3; l++) {
        k_edge<<<NB_E, 256>>>(eidx, eidx + EE, l);
        k_nodeZ<<<NB_Z, 256>>>(W1 + l * 162, b1 + l * 18, eps_gin + l, l);
        k_nodeY<<<NB_N, 256>>>(W1 + l * 162, b1 + l * 18, W2 + l * 162, b2 + l * 9,
                               bn1_g + l * 18, bn1_b + l * 18, l);
        if (l < 2) {
            k_vnA<<<NB_G, 256>>>(vnW1 + l * 162, vnb1 + l * 18, l);
            k_vnB<<<NB_G, 256>>>(vnW1 + l * 162, vnb1 + l * 18, vnW2 + l * 162,
                                 vnb2 + l * 9, vnbn1_g + l * 18, vnbn1_b + l * 18, l);
            k_vnC<<<NB_G, 256>>>(vnbn2_g + l * 9, vnbn2_b + l * 9, l);
            k_final_mid<<<NB_N, 256>>>(batch, bno_g + l * 9, bno_b + l * 9, l,
                                       (l == 0) ? 1 : 0);
        } else {
            k_final_last<<<NB_N, 256>>>(bno_g + l * 9, bno_b + l * 9, l);
        }
    }
    k_out<<<1, 32>>>((float*)d_out);
}

// round 15
// speedup vs baseline: 2.9719x; 1.0917x over previous
#include <cuda_runtime.h>
#include <cuda_fp16.h>

#define NN 1048576
#define EE 8388608
#define GG 32768
#define PS 12   // fp32 row stride for graph arrays (9 ch + 3 pad) -> 48B
#define HS 16   // fp16 row stride in halves -> 32B (1 sector)
#define NZI 8                           // nodes/thread in k_nodeZ (R6-proven full unroll)
#define NB_Z (NN / (256 * NZI))         // 512
#define NB_N (NN / 256)                 // 4096
#define NB_E (EE / 256)                 // 32768
#define NB_G (GG / 256)                 // 128

// ---------------- device state (no allocation allowed) ----------------
__device__ __align__(32) __half g_h16[(size_t)NN * HS];   // fp16 h_in (residual + gather source)
__device__ __align__(32) __half g_ab [(size_t)NN * HS];   // fp16 edge-aggr accumulator
__device__ __align__(32) __half g_zb [(size_t)NN * HS];   // fp16 z / z2 inter-kernel buffer
__device__ __align__(16) float  g_vn [(size_t)GG * PS];
__device__ __align__(16) float  g_gs [(size_t)GG * PS];
__device__ unsigned char g_eb[(size_t)EE];                // packed edge attr codes (<216)
__device__ __align__(32) __half g_bt16[3 * 216 * 16];     // fp16 combined bond tables
// per-layer raw BN stats: sum at [c], sumsq at [18+c], 36-stride per layer
__device__ double g_stZ1[3 * 36];
__device__ double g_stZ2[3 * 36];
__device__ double g_stV1[2 * 36];
__device__ double g_stV2[2 * 36];
__device__ double g_outacc[9];

// ---------------- helpers ----------------
__device__ __forceinline__ void red_add4(float* p, float a, float b, float c, float d) {
    asm volatile("red.global.add.v4.f32 [%0], {%1,%2,%3,%4};"
                 :: "l"(__cvta_generic_to_global(p)), "f"(a), "f"(b), "f"(c), "f"(d) : "memory");
}
__device__ __forceinline__ void red_add1(float* p, float a) {
    asm volatile("red.global.add.f32 [%0], %1;"
                 :: "l"(__cvta_generic_to_global(p)), "f"(a) : "memory");
}
__device__ __forceinline__ void red_add_h2v4(__half* p, unsigned a, unsigned b,
                                             unsigned c, unsigned d) {
    asm volatile("red.global.add.noftz.v4.f16x2 [%0], {%1,%2,%3,%4};"
                 :: "l"(__cvta_generic_to_global(p)), "r"(a), "r"(b), "r"(c), "r"(d) : "memory");
}
__device__ __forceinline__ void red_add_h2(__half* p, unsigned a) {
    asm volatile("red.global.add.noftz.f16x2 [%0], %1;"
                 :: "l"(__cvta_generic_to_global(p)), "r"(a) : "memory");
}
__device__ __forceinline__ float warp_sum(float v) {
    #pragma unroll
    for (int off = 16; off > 0; off >>= 1) v += __shfl_down_sync(0xffffffffu, v, off);
    return v;
}

// store 9 floats as a 32B fp16 row AND return the rounded values (for consistent stats)
__device__ __forceinline__ void store_h16_rounded(__half* basePtr, int n,
                                                  const float* h, float* hr) {
    __half2 hh[8];
    hh[0] = __floats2half2_rn(h[0], h[1]);
    hh[1] = __floats2half2_rn(h[2], h[3]);
    hh[2] = __floats2half2_rn(h[4], h[5]);
    hh[3] = __floats2half2_rn(h[6], h[7]);
    hh[4] = __floats2half2_rn(h[8], 0.f);
    hh[5] = hh[6] = hh[7] = __floats2half2_rn(0.f, 0.f);
    uint4* sp = (uint4*)(basePtr + (size_t)n * HS);
    sp[0] = *(uint4*)&hh[0];
    sp[1] = *(uint4*)&hh[4];
    if (hr) {
        float2 r0 = __half22float2(hh[0]), r1 = __half22float2(hh[1]);
        float2 r2 = __half22float2(hh[2]), r3 = __half22float2(hh[3]);
        float2 r4 = __half22float2(hh[4]);
        hr[0] = r0.x; hr[1] = r0.y; hr[2] = r1.x; hr[3] = r1.y;
        hr[4] = r2.x; hr[5] = r2.y; hr[6] = r3.x; hr[7] = r3.y; hr[8] = r4.x;
    }
}
__device__ __forceinline__ void store_h16(__half* basePtr, int n, const float* h) {
    store_h16_rounded(basePtr, n, h, (float*)0);
}
__device__ __forceinline__ void load_h16(const __half* basePtr, int n, float* out) {
    const uint4* ap = (const uint4*)(basePtr + (size_t)n * HS);
    uint4 u0 = ap[0];
    unsigned int u8 = *(const unsigned int*)(ap + 1);
    float2 a0 = __half22float2(*(__half2*)&u0.x);
    float2 a1 = __half22float2(*(__half2*)&u0.y);
    float2 a2 = __half22float2(*(__half2*)&u0.z);
    float2 a3 = __half22float2(*(__half2*)&u0.w);
    float2 a4 = __half22float2(*(__half2*)&u8);
    out[0] = a0.x; out[1] = a0.y; out[2] = a1.x; out[3] = a1.y;
    out[4] = a2.x; out[5] = a2.y; out[6] = a3.x; out[7] = a3.y; out[8] = a4.x;
}
__device__ __forceinline__ void zero_h16(__half* basePtr, int n) {
    uint4 z = make_uint4(0u, 0u, 0u, 0u);
    uint4* sp = (uint4*)(basePtr + (size_t)n * HS);
    sp[0] = z; sp[1] = z;
}

// warp-level segmented sum over sorted keys, then 3 vector atomics per segment head
__device__ __forceinline__ void seg_atomic9(int key, float v[9], float* dstBase) {
    int lane = threadIdx.x & 31;
    #pragma unroll
    for (int off = 1; off < 32; off <<= 1) {
        int nk = __shfl_down_sync(0xffffffffu, key, off);
        float t[9];
        #pragma unroll
        for (int k = 0; k < 9; k++) t[k] = __shfl_down_sync(0xffffffffu, v[k], off);
        if (lane + off < 32 && nk == key) {
            #pragma unroll
            for (int k = 0; k < 9; k++) v[k] += t[k];
        }
    }
    int pk = __shfl_up_sync(0xffffffffu, key, 1);
    if (lane == 0 || pk != key) {
        float* p = dstBase + (size_t)key * PS;
        red_add4(p,     v[0], v[1], v[2], v[3]);
        red_add4(p + 4, v[4], v[5], v[6], v[7]);
        red_add1(p + 8, v[8]);
    }
}

// inline BN param computation: threads c<C write sP[c]=scale, sP[C+c]=shift.
__device__ __forceinline__ void compute_bn(const double* st, int C, double inv,
                                           const float* gamma, const float* beta,
                                           float* sP) {
    int c = threadIdx.x;
    if (c < C) {
        double mean = st[c] * inv;
        double var  = st[18 + c] * inv - mean * mean;
        float sc = __ldg(gamma + c) * rsqrtf((float)var + 1e-5f);
        sP[c] = sc;
        sP[C + c] = __ldg(beta + c) - (float)mean * sc;
    }
}

// flush register stats (C channels of s,q) to global double slot via smem racc[36]
__device__ __forceinline__ void stats_flush(const float* s, const float* q, int C,
                                            double* st, float* racc) {
    int lane = threadIdx.x & 31;
    for (int c = 0; c < C; c++) {
        float ss = warp_sum(s[c]);
        float qq = warp_sum(q[c]);
        if (lane == 0) { atomicAdd(&racc[c], ss); atomicAdd(&racc[18 + c], qq); }
    }
    __syncthreads();
    int t = threadIdx.x;
    if (t < C) atomicAdd(&st[t], (double)racc[t]);
    if (t >= 18 && t < 18 + C) atomicAdd(&st[t], (double)racc[t]);
}

// ---------------- kernels ----------------
__global__ void __launch_bounds__(256) k_init() {
    int i = blockIdx.x * 256 + threadIdx.x;
    if (i < GG * PS) { g_vn[i] = 0.f; g_gs[i] = 0.f; }
    if (i < 108) { g_stZ1[i] = 0.0; g_stZ2[i] = 0.0; }
    if (i < 72)  { g_stV1[i] = 0.0; g_stV2[i] = 0.0; }
    if (i < 9)   g_outacc[i] = 0.0;
}

// pack edge attrs: code = a0 + 6*a1 + 36*a2  (< 216), 1 byte per edge (run once)
__global__ void __launch_bounds__(256) k_pack(const int* __restrict__ ea) {
    int e = blockIdx.x * 256 + threadIdx.x;
    int a0 = __ldg(ea + (size_t)3 * e);
    int a1 = __ldg(ea + (size_t)3 * e + 1);
    int a2 = __ldg(ea + (size_t)3 * e + 2);
    g_eb[e] = (unsigned char)(a0 + 6 * a1 + 36 * a2);
}

// build fp16 combined bond tables for ALL 3 layers (one launch, 3 blocks)
__global__ void k_btab3(const float* __restrict__ bond_all) {
    const float* bond = bond_all + blockIdx.x * 162;
    __half* bt = g_bt16 + blockIdx.x * (216 * 16);
    for (int i = threadIdx.x; i < 216 * 16; i += 256) {
        int code = i / 16, k = i % 16;
        float v = 0.f;
        if (k < 9) {
            int a0 = code % 6, a1 = (code / 6) % 6, a2 = code / 36;
            v = __ldg(bond + a0 * 9 + k) + __ldg(bond + 54 + a1 * 9 + k)
              + __ldg(bond + 108 + a2 * 9 + k);
        }
        bt[i] = __float2half(v);
    }
}

// AtomEncoder: h = sum_f atom_emb[f, x[n,f]]; write fp16 h; zero aggr buf; graph sums
__global__ void __launch_bounds__(256) k_atom(const float* __restrict__ atom_emb,
                                              const int* __restrict__ x,
                                              const int* __restrict__ batch) {
    int n = blockIdx.x * 256 + threadIdx.x;
    float h[9];
    #pragma unroll
    for (int k = 0; k < 9; k++) h[k] = 0.f;
    #pragma unroll
    for (int f = 0; f < 9; f++) {
        int v = __ldg(x + (size_t)n * 9 + f);
        const float* row = atom_emb + ((size_t)f * 119 + v) * 9;
        #pragma unroll
        for (int k = 0; k < 9; k++) h[k] += __ldg(row + k);
    }
    float hr[9];
    store_h16_rounded(g_h16, n, h, hr);
    zero_h16(g_ab, n);
    int g = __ldg(batch + n);
    seg_atomic9(g, hr, g_gs);   // graph sums of the rounded h (what nodes carry)
}

// GIN message: relu(h16[src] + bt16[code]) in fp16x2 -> fp16 atomics into g_ab[dst].
// 1-sector gather + 1-sector table read + 1-sector scatter; zero conversions.
__global__ void __launch_bounds__(256) k_edge(const int* __restrict__ src,
                                              const int* __restrict__ dst, int l) {
    const __half* bt = g_bt16 + l * (216 * 16);
    int e = blockIdx.x * 256 + threadIdx.x;
    int s = __ldg(src + e);
    int d = __ldg(dst + e);
    int code = (int)g_eb[e];
    const uint4* hp = (const uint4*)(g_h16 + (size_t)s * HS);
    uint4 u0 = __ldg(hp);
    unsigned int u8 = __ldg((const unsigned int*)(hp + 1));
    const uint4* tb = (const uint4*)(bt + code * 16);
    uint4 t0 = __ldg(tb);
    unsigned int t8 = __ldg((const unsigned int*)(tb + 1));
    __half2 zz = __float2half2_rn(0.f);
    __half2 r0 = __hmax2(__hadd2(*(__half2*)&u0.x, *(__half2*)&t0.x), zz);
    __half2 r1 = __hmax2(__hadd2(*(__half2*)&u0.y, *(__half2*)&t0.y), zz);
    __half2 r2 = __hmax2(__hadd2(*(__half2*)&u0.z, *(__half2*)&t0.z), zz);
    __half2 r3 = __hmax2(__hadd2(*(__half2*)&u0.w, *(__half2*)&t0.w), zz);
    __half2 r4 = __hmax2(__hadd2(*(__half2*)&u8,   *(__half2*)&t8),   zz);
    __half* ab = g_ab + (size_t)d * HS;
    red_add_h2v4(ab, *(unsigned*)&r0, *(unsigned*)&r1, *(unsigned*)&r2, *(unsigned*)&r3);
    red_add_h2(ab + 8, *(unsigned*)&r4);
}

// z = (1+eps)*h16 + aggr(fp16) ; write z (fp16, rounded) ; stats on ROUNDED z@W1+b1
// R6-proven form: NZI=8 fully unrolled, no reg cap
__global__ void __launch_bounds__(256) k_nodeZ(const float* __restrict__ W1,
                                               const float* __restrict__ b1,
                                               const float* __restrict__ eps_ptr, int l) {
    __shared__ float sW[162], sb[18], racc[36];
    int t = threadIdx.x;
    if (t < 162) sW[t] = W1[t];
    if (t < 18)  sb[t] = b1[t];
    if (t < 36)  racc[t] = 0.f;
    __syncthreads();
    float eps1 = 1.f + __ldg(eps_ptr);
    float s[18], q[18];
    #pragma unroll
    for (int c = 0; c < 18; c++) { s[c] = 0.f; q[c] = 0.f; }
    int base = blockIdx.x * (256 * NZI) + t;
    #pragma unroll
    for (int i = 0; i < NZI; i++) {
        int n = base + i * 256;
        float a9[9], h9[9];
        load_h16(g_ab, n, a9);
        load_h16(g_h16, n, h9);
        float z[9];
        #pragma unroll
        for (int k = 0; k < 9; k++) z[k] = fmaf(eps1, h9[k], a9[k]);
        float zr[9];
        store_h16_rounded(g_zb, n, z, zr);   // rounded values = what nodeY will read
        #pragma unroll
        for (int c = 0; c < 18; c++) {
            float z1 = sb[c];
            #pragma unroll
            for (int j = 0; j < 9; j++) z1 = fmaf(zr[j], sW[j * 18 + c], z1);
            s[c] += z1;
            q[c] = fmaf(z1, z1, q[c]);
        }
    }
    stats_flush(s, q, 18, g_stZ1 + l * 36, racc);
}

// y = relu(BN1(z@W1+b1)) (inline params); z2 = y@W2+b2; write z2 (fp16, rounded);
// stats on ROUNDED z2 (what final reads)
__global__ void __launch_bounds__(256) k_nodeY(const float* __restrict__ W1,
                                               const float* __restrict__ b1,
                                               const float* __restrict__ W2,
                                               const float* __restrict__ b2,
                                               const float* __restrict__ bn1_g,
                                               const float* __restrict__ bn1_b, int l) {
    __shared__ float sW1[162], sW2[162], sb1[18], sb2[9], sP[36], racc[36];
    int t = threadIdx.x;
    if (t < 162) { sW1[t] = W1[t]; sW2[t] = W2[t]; }
    if (t < 18) sb1[t] = b1[t];
    if (t < 9)  sb2[t] = b2[t];
    if (t < 36) racc[t] = 0.f;
    compute_bn(g_stZ1 + l * 36, 18, 1.0 / (double)NN, bn1_g, bn1_b, sP);
    __syncthreads();
    int n = blockIdx.x * 256 + t;
    float z[9];
    load_h16(g_zb, n, z);
    float z2[9];
    #pragma unroll
    for (int c = 0; c < 9; c++) z2[c] = sb2[c];
    #pragma unroll
    for (int c = 0; c < 18; c++) {
        float z1 = sb1[c];
        #pragma unroll
        for (int j = 0; j < 9; j++) z1 = fmaf(z[j], sW1[j * 18 + c], z1);
        float y = fmaxf(fmaf(z1, sP[c], sP[18 + c]), 0.f);
        #pragma unroll
        for (int j = 0; j < 9; j++) z2[j] = fmaf(y, sW2[c * 9 + j], z2[j]);
    }
    float z2r[9];
    store_h16_rounded(g_zb, n, z2, z2r);
    int lane = t & 31;
    #pragma unroll
    for (int c = 0; c < 9; c++) {
        float ss = warp_sum(z2r[c]);
        float qq = warp_sum(z2r[c] * z2r[c]);
        if (lane == 0) { atomicAdd(&racc[c], ss); atomicAdd(&racc[18 + c], qq); }
    }
    __syncthreads();
    double* st = g_stZ2 + l * 36;
    if (t < 9) atomicAdd(&st[t], (double)racc[t]);
    if (t >= 18 && t < 27) atomicAdd(&st[t], (double)racc[t]);
}

// VN step A
__global__ void __launch_bounds__(256) k_vnA(const float* __restrict__ W1,
                                             const float* __restrict__ b1, int l) {
    __shared__ float sW[162], sb[18], racc[36];
    int t = threadIdx.x;
    if (t < 162) sW[t] = W1[t];
    if (t < 18)  sb[t] = b1[t];
    if (t < 36)  racc[t] = 0.f;
    __syncthreads();
    int g = blockIdx.x * 256 + t;
    float4* gp = (float4*)(g_gs + (size_t)g * PS);
    const float4* vp = (const float4*)(g_vn + (size_t)g * PS);
    float4 a = gp[0], b4 = gp[1], c4 = gp[2];
    float4 va = vp[0], vb = vp[1], vc = vp[2];
    float vt[9] = {a.x + va.x, a.y + va.y, a.z + va.z, a.w + va.w,
                   b4.x + vb.x, b4.y + vb.y, b4.z + vb.z, b4.w + vb.w, c4.x + vc.x};
    gp[0] = make_float4(vt[0], vt[1], vt[2], vt[3]);
    gp[1] = make_float4(vt[4], vt[5], vt[6], vt[7]);
    gp[2] = make_float4(vt[8], 0.f, 0.f, 0.f);
    float s[18], q[18];
    #pragma unroll
    for (int c = 0; c < 18; c++) {
        float u = sb[c];
        #pragma unroll
        for (int j = 0; j < 9; j++) u = fmaf(vt[j], sW[j * 18 + c], u);
        s[c] = u; q[c] = u * u;
    }
    stats_flush(s, q, 18, g_stV1 + l * 36, racc);
}

// VN step B
__global__ void __launch_bounds__(256) k_vnB(const float* __restrict__ W1,
                                             const float* __restrict__ b1,
                                             const float* __restrict__ W2,
                                             const float* __restrict__ b2,
                                             const float* __restrict__ bn_g,
                                             const float* __restrict__ bn_b, int l) {
    __shared__ float sW1[162], sW2[162], sb1[18], sb2[9], sP[36], racc[36];
    int t = threadIdx.x;
    if (t < 162) { sW1[t] = W1[t]; sW2[t] = W2[t]; }
    if (t < 18) sb1[t] = b1[t];
    if (t < 9)  sb2[t] = b2[t];
    if (t < 36) racc[t] = 0.f;
    compute_bn(g_stV1 + l * 36, 18, 1.0 / (double)GG, bn_g, bn_b, sP);
    __syncthreads();
    int g = blockIdx.x * 256 + t;
    float4* gp = (float4*)(g_gs + (size_t)g * PS);
    float4 a = gp[0], b4 = gp[1], c4 = gp[2];
    float vt[9] = {a.x, a.y, a.z, a.w, b4.x, b4.y, b4.z, b4.w, c4.x};
    float u2[9];
    #pragma unroll
    for (int c = 0; c < 9; c++) u2[c] = sb2[c];
    #pragma unroll
    for (int c = 0; c < 18; c++) {
        float u = sb1[c];
        #pragma unroll
        for (int j = 0; j < 9; j++) u = fmaf(vt[j], sW1[j * 18 + c], u);
        float y = fmaxf(fmaf(u, sP[c], sP[18 + c]), 0.f);
        #pragma unroll
        for (int j = 0; j < 9; j++) u2[j] = fmaf(y, sW2[c * 9 + j], u2[j]);
    }
    gp[0] = make_float4(u2[0], u2[1], u2[2], u2[3]);
    gp[1] = make_float4(u2[4], u2[5], u2[6], u2[7]);
    gp[2] = make_float4(u2[8], 0.f, 0.f, 0.f);
    float s[9], q[9];
    #pragma unroll
    for (int c = 0; c < 9; c++) { s[c] = u2[c]; q[c] = u2[c] * u2[c]; }
    stats_flush(s, q, 9, g_stV2 + l * 36, racc);
}

// VN step C
__global__ void __launch_bounds__(256) k_vnC(const float* __restrict__ bn_g,
                                             const float* __restrict__ bn_b, int l) {
    __shared__ float sP[18];
    compute_bn(g_stV2 + l * 36, 9, 1.0 / (double)GG, bn_g, bn_b, sP);
    __syncthreads();
    int g = blockIdx.x * 256 + threadIdx.x;
    float4* gp = (float4*)(g_gs + (size_t)g * PS);
    float4* vp = (float4*)(g_vn + (size_t)g * PS);
    float4 a = gp[0], b4 = gp[1], c4 = gp[2];
    float u2[9] = {a.x, a.y, a.z, a.w, b4.x, b4.y, b4.z, b4.w, c4.x};
    float4 va = vp[0], vb = vp[1], vc = vp[2];
    float vo[9] = {va.x, va.y, va.z, va.w, vb.x, vb.y, vb.z, vb.w, vc.x};
    #pragma unroll
    for (int k = 0; k < 9; k++)
        vo[k] += fmaxf(fmaf(u2[k], sP[k], sP[9 + k]), 0.f);
    vp[0] = make_float4(vo[0], vo[1], vo[2], vo[3]);
    vp[1] = make_float4(vo[4], vo[5], vo[6], vo[7]);
    vp[2] = make_float4(vo[8], 0.f, 0.f, 0.f);
    float4 zz = make_float4(0.f, 0.f, 0.f, 0.f);
    gp[0] = zz; gp[1] = zz; gp[2] = zz;
}

// layer finish (l<2): h_new = relu(BNout(z2)) + h16; h_in' = h_new + vn'[batch];
// write fp16 h row; zero aggr buffer for next layer
__global__ void __launch_bounds__(256) k_final_mid(const int* __restrict__ batch,
                                                   const float* __restrict__ bn_g,
                                                   const float* __restrict__ bn_b,
                                                   int l, int accumGS) {
    __shared__ float sP[18];
    compute_bn(g_stZ2 + l * 36, 9, 1.0 / (double)NN, bn_g, bn_b, sP);
    __syncthreads();
    int n = blockIdx.x * 256 + threadIdx.x;
    float z2[9], hi[9];
    load_h16(g_zb, n, z2);
    load_h16(g_h16, n, hi);
    int g = __ldg(batch + n);
    const float4* vp = (const float4*)(g_vn + (size_t)g * PS);
    float4 va = vp[0], vb = vp[1], vc = vp[2];
    float vn9[9] = {va.x, va.y, va.z, va.w, vb.x, vb.y, vb.z, vb.w, vc.x};
    float hx[9];
    #pragma unroll
    for (int k = 0; k < 9; k++) {
        float zn = fmaxf(fmaf(z2[k], sP[k], sP[9 + k]), 0.f);
        hx[k] = zn + hi[k] + vn9[k];
    }
    float hr[9];
    store_h16_rounded(g_h16, n, hx, hr);
    zero_h16(g_ab, n);
    if (accumGS) seg_atomic9(g, hr, g_gs);
}

// last layer finish: h = BNout(z2) + h16 (no relu); global sum
__global__ void __launch_bounds__(256) k_final_last(const float* __restrict__ bn_g,
                                                    const float* __restrict__ bn_b, int l) {
    __shared__ float sP[18], racc[9];
    compute_bn(g_stZ2 + l * 36, 9, 1.0 / (double)NN, bn_g, bn_b, sP);
    if (threadIdx.x < 9) racc[threadIdx.x] = 0.f;
    __syncthreads();
    int n = blockIdx.x * 256 + threadIdx.x;
    float z2[9], hi[9];
    load_h16(g_zb, n, z2);
    load_h16(g_h16, n, hi);
    int lane = threadIdx.x & 31;
    #pragma unroll
    for (int k = 0; k < 9; k++) {
        float h = fmaf(z2[k], sP[k], sP[9 + k]) + hi[k];
        float v = warp_sum(h);
        if (lane == 0) atomicAdd(&racc[k], v);
    }
    __syncthreads();
    if (threadIdx.x < 9) atomicAdd(&g_outacc[threadIdx.x], (double)racc[threadIdx.x]);
}

__global__ void k_out(float* __restrict__ out) {
    if (threadIdx.x < 9) out[threadIdx.x] = (float)g_outacc[threadIdx.x];
}

// ---------------- host ----------------
extern "C" void kernel_launch(void* const* d_in, const int* in_sizes, int n_in,
                              void* d_out, int out_size) {
    const float* atom_emb = (const float*)d_in[0];
    const float* bond_emb = (const float*)d_in[1];
    const float* eps_gin  = (const float*)d_in[2];
    const float* W1       = (const float*)d_in[3];
    const float* b1       = (const float*)d_in[4];
    const float* bn1_g    = (const float*)d_in[5];
    const float* bn1_b    = (const float*)d_in[6];
    const float* W2       = (const float*)d_in[7];
    const float* b2       = (const float*)d_in[8];
    const float* bno_g    = (const float*)d_in[9];
    const float* bno_b    = (const float*)d_in[10];
    const float* vnW1     = (const float*)d_in[11];
    const float* vnb1     = (const float*)d_in[12];
    const float* vnbn1_g  = (const float*)d_in[13];
    const float* vnbn1_b  = (const float*)d_in[14];
    const float* vnW2     = (const float*)d_in[15];
    const float* vnb2     = (const float*)d_in[16];
    const float* vnbn2_g  = (const float*)d_in[17];
    const float* vnbn2_b  = (const float*)d_in[18];
    const int*   x        = (const int*)d_in[19];
    const int*   eidx     = (const int*)d_in[20];
    const int*   eattr    = (const int*)d_in[21];
    const int*   batch    = (const int*)d_in[22];
    (void)in_sizes; (void)n_in; (void)out_size;

    k_init<<<(GG * PS + 255) / 256, 256>>>();
    k_pack<<<NB_E, 256>>>(eattr);
    k_btab3<<<3, 256>>>(bond_emb);
    k_atom<<<NB_N, 256>>>(atom_emb, x, batch);

    for (int l = 0; l < 3; l++) {
        k_edge<<<NB_E, 256>>>(eidx, eidx + EE, l);
        k_nodeZ<<<NB_Z, 256>>>(W1 + l * 162, b1 + l * 18, eps_gin + l, l);
        k_nodeY<<<NB_N, 256>>>(W1 + l * 162, b1 + l * 18, W2 + l * 162, b2 + l * 9,
                               bn1_g + l * 18, bn1_b + l * 18, l);
        if (l < 2) {
            k_vnA<<<NB_G, 256>>>(vnW1 + l * 162, vnb1 + l * 18, l);
            k_vnB<<<NB_G, 256>>>(vnW1 + l * 162, vnb1 + l * 18, vnW2 + l * 162,
                                 vnb2 + l * 9, vnbn1_g + l * 18, vnbn1_b + l * 18, l);
            k_vnC<<<NB_G, 256>>>(vnbn2_g + l * 9, vnbn2_b + l * 9, l);
            k_final_mid<<<NB_N, 256>>>(batch, bno_g + l * 9, bno_b + l * 9, l,
                                       (l == 0) ? 1 : 0);
        } else {
            k_final_last<<<NB_N, 256>>>(bno_g + l * 9, bno_b + l * 9, l);
        }
    }
    k_out<<<1, 32>>>((float*)d_out);
}